// round 1
// baseline (speedup 1.0000x reference)
#include <cuda_runtime.h>
#include <cstddef>

// Problem constants
#define BB   4
#define LL   1024
#define HH   16
#define DD   64
#define EMBN 1024
#define MAXREL 512

// Scratch (allocation-free rule: device globals)
__device__ float g_q[BB*LL*HH*DD];
__device__ float g_k[BB*LL*HH*DD];
__device__ float g_v[BB*LL*HH*DD];
__device__ float g_ctx[BB*LL*HH*DD];

#define SK  68    // padded row stride for 64-wide fp32 tiles (16B aligned, 2-way max conflicts)
#define SSB 129   // stride for 128-wide band buffer (scalar access only)

// ---------------------------------------------------------------------------
// Projection: out[r, d] = sum_e X[r, e] * W[d, e] + b[d]
// rows r = ((b*L + l)*H + h), 65536 rows total, K = N = 64.
// grid (1024, 3): y selects q/k/v
// ---------------------------------------------------------------------------
__global__ __launch_bounds__(256) void proj_kernel(
    const float* __restrict__ query, const float* __restrict__ key_, const float* __restrict__ value,
    const float* __restrict__ Wq, const float* __restrict__ bq,
    const float* __restrict__ Wk, const float* __restrict__ bk,
    const float* __restrict__ Wv, const float* __restrict__ bv)
{
    __shared__ float Xs[64*SK];
    __shared__ float Ws[64*SK];
    __shared__ float bs[64];

    const float* X; const float* W; const float* bias; float* out;
    if (blockIdx.y == 0)      { X = query; W = Wq; bias = bq; out = g_q; }
    else if (blockIdx.y == 1) { X = key_;  W = Wk; bias = bk; out = g_k; }
    else                      { X = value; W = Wv; bias = bv; out = g_v; }

    const int tid = threadIdx.x;
    const size_t r0 = (size_t)blockIdx.x * 64;

    #pragma unroll
    for (int t = 0; t < 4; t++) {
        int idx = tid + t*256;
        int rr = idx >> 4, cc = (idx & 15) << 2;
        *(float4*)&Xs[rr*SK + cc] = *(const float4*)(X + (r0 + rr)*64 + cc);
        *(float4*)&Ws[rr*SK + cc] = *(const float4*)(W + (size_t)rr*64 + cc);
    }
    if (tid < 64) bs[tid] = bias[tid];
    __syncthreads();

    const int ty = tid >> 4, tx = tid & 15;
    float acc[4][4] = {};
    for (int e = 0; e < 64; e += 4) {
        float4 a[4], bb[4];
        #pragma unroll
        for (int ii = 0; ii < 4; ii++) a[ii]  = *(const float4*)&Xs[(ty + 16*ii)*SK + e];
        #pragma unroll
        for (int jj = 0; jj < 4; jj++) bb[jj] = *(const float4*)&Ws[(tx + 16*jj)*SK + e];
        #pragma unroll
        for (int ii = 0; ii < 4; ii++)
            #pragma unroll
            for (int jj = 0; jj < 4; jj++)
                acc[ii][jj] += a[ii].x*bb[jj].x + a[ii].y*bb[jj].y
                             + a[ii].z*bb[jj].z + a[ii].w*bb[jj].w;
    }
    #pragma unroll
    for (int ii = 0; ii < 4; ii++) {
        int i = ty + 16*ii;
        #pragma unroll
        for (int jj = 0; jj < 4; jj++) {
            int d = tx + 16*jj;
            out[(r0 + i)*64 + d] = acc[ii][jj] + bs[d];
        }
    }
}

// ---------------------------------------------------------------------------
// Flash attention with relative-position K/V bias.
// One block per (q-block of 64, head, batch). 256 threads.
// ---------------------------------------------------------------------------
#define ATT_SMEM_WORDS (4*64*SK + 2*128*SK + 64*SSB + 64*64)
#define ATT_SMEM_BYTES (ATT_SMEM_WORDS * 4)

__global__ __launch_bounds__(256) void attn_kernel(
    const int*   __restrict__ mask,
    const float* __restrict__ relk,
    const float* __restrict__ relv)
{
    extern __shared__ float sm[];
    float* Qs  = sm;                 // 64 x SK
    float* Ks  = Qs  + 64*SK;        // 64 x SK
    float* Vs  = Ks  + 64*SK;        // 64 x SK
    float* Pn  = Vs  + 64*SK;        // 64 x SK   (probabilities, natural layout)
    float* Tkw = Pn  + 64*SK;        // 128 x SK  (rel_k window rows)
    float* Tvw = Tkw + 128*SK;       // 128 x SK  (rel_v window rows)
    float* SB  = Tvw + 128*SK;       // 64 x SSB  (Srel, then band probabilities)
    int*   Ms  = (int*)(SB + 64*SSB);// 64 x 64

    const int b  = blockIdx.z;
    const int h  = blockIdx.y;
    const int q0 = blockIdx.x * 64;
    const int tid = threadIdx.x;
    const int ty = tid >> 4, tx = tid & 15;

    // Load Q tile
    #pragma unroll
    for (int t = 0; t < 4; t++) {
        int idx = tid + t*256;
        int rr = idx >> 4, cc = (idx & 15) << 2;
        *(float4*)&Qs[rr*SK + cc] =
            *(const float4*)(g_q + (((size_t)(b*LL + q0 + rr)*HH + h) << 6) + cc);
    }

    float accv[4][4] = {};
    float mrow[4] = {-1e30f, -1e30f, -1e30f, -1e30f};
    float lrow[4] = {};

    for (int kt = 0; kt < 16; kt++) {
        const int k0 = kt * 64;
        const int d0 = k0 - q0;

        // ---- stage K, V, mask, rel windows ----
        #pragma unroll
        for (int t = 0; t < 4; t++) {
            int idx = tid + t*256;
            int rr = idx >> 4, cc = (idx & 15) << 2;
            size_t base = ((size_t)(b*LL + k0 + rr)*HH + h) << 6;
            *(float4*)&Ks[rr*SK + cc] = *(const float4*)(g_k + base + cc);
            *(float4*)&Vs[rr*SK + cc] = *(const float4*)(g_v + base + cc);
            *(int4*)&Ms[rr*64 + cc] =
                *(const int4*)(mask + ((size_t)b*LL + q0 + rr)*LL + k0 + cc);
        }
        #pragma unroll
        for (int t = 0; t < 8; t++) {
            int idx = tid + t*256;
            int rr = idx >> 4, cc = (idx & 15) << 2;
            int diff = d0 + rr - 63;
            diff = diff < -MAXREL ? -MAXREL : (diff > MAXREL ? MAXREL : diff);
            size_t row = (size_t)(diff + MAXREL) * 64;
            *(float4*)&Tkw[rr*SK + cc] = *(const float4*)(relk + row + cc);
            *(float4*)&Tvw[rr*SK + cc] = *(const float4*)(relv + row + cc);
        }
        __syncthreads();

        // ---- Srel = Q @ Tkw^T  (64 x 128) ----
        {
            float sr[4][8] = {};
            for (int e = 0; e < 64; e += 4) {
                float4 a[4], bb[8];
                #pragma unroll
                for (int ii = 0; ii < 4; ii++) a[ii]  = *(const float4*)&Qs[(ty + 16*ii)*SK + e];
                #pragma unroll
                for (int jj = 0; jj < 8; jj++) bb[jj] = *(const float4*)&Tkw[(tx + 16*jj)*SK + e];
                #pragma unroll
                for (int ii = 0; ii < 4; ii++)
                    #pragma unroll
                    for (int jj = 0; jj < 8; jj++)
                        sr[ii][jj] += a[ii].x*bb[jj].x + a[ii].y*bb[jj].y
                                    + a[ii].z*bb[jj].z + a[ii].w*bb[jj].w;
            }
            #pragma unroll
            for (int ii = 0; ii < 4; ii++)
                #pragma unroll
                for (int jj = 0; jj < 8; jj++)
                    SB[(ty + 16*ii)*SSB + (tx + 16*jj)] = sr[ii][jj];
        }
        __syncthreads();

        // ---- S1 = Q @ K^T, assemble score, online softmax ----
        float p[4][4];
        {
            float s[4][4] = {};
            for (int e = 0; e < 64; e += 4) {
                float4 a[4], bb[4];
                #pragma unroll
                for (int ii = 0; ii < 4; ii++) a[ii]  = *(const float4*)&Qs[(ty + 16*ii)*SK + e];
                #pragma unroll
                for (int jj = 0; jj < 4; jj++) bb[jj] = *(const float4*)&Ks[(tx + 16*jj)*SK + e];
                #pragma unroll
                for (int ii = 0; ii < 4; ii++)
                    #pragma unroll
                    for (int jj = 0; jj < 4; jj++)
                        s[ii][jj] += a[ii].x*bb[jj].x + a[ii].y*bb[jj].y
                                   + a[ii].z*bb[jj].z + a[ii].w*bb[jj].w;
            }
            #pragma unroll
            for (int ii = 0; ii < 4; ii++) {
                int i = ty + 16*ii;
                #pragma unroll
                for (int jj = 0; jj < 4; jj++) {
                    int j = tx + 16*jj;
                    float v = Ms[i*64 + j] ? s[ii][jj] : -1e20f;
                    v += SB[i*SSB + (j - i + 63)];
                    s[ii][jj] = v * 0.125f;
                }
            }
            #pragma unroll
            for (int ii = 0; ii < 4; ii++) {
                float rm = fmaxf(fmaxf(s[ii][0], s[ii][1]), fmaxf(s[ii][2], s[ii][3]));
                #pragma unroll
                for (int o = 1; o < 16; o <<= 1)
                    rm = fmaxf(rm, __shfl_xor_sync(0xffffffffu, rm, o));
                float mn  = fmaxf(mrow[ii], rm);
                float csc = __expf(mrow[ii] - mn);
                mrow[ii] = mn;
                lrow[ii] *= csc;
                #pragma unroll
                for (int dd = 0; dd < 4; dd++) accv[ii][dd] *= csc;
                float ls = 0.f;
                #pragma unroll
                for (int jj = 0; jj < 4; jj++) {
                    p[ii][jj] = __expf(s[ii][jj] - mn);
                    ls += p[ii][jj];
                }
                lrow[ii] += ls;
            }
            #pragma unroll
            for (int ii = 0; ii < 4; ii++)
                #pragma unroll
                for (int jj = 0; jj < 4; jj++)
                    Pn[(ty + 16*ii)*SK + (tx + 16*jj)] = p[ii][jj];
        }
        __syncthreads();

        // ---- re-use SB as band probability matrix ----
        for (int t = tid; t < 64*SSB; t += 256) SB[t] = 0.0f;
        __syncthreads();
        #pragma unroll
        for (int ii = 0; ii < 4; ii++) {
            int i = ty + 16*ii;
            #pragma unroll
            for (int jj = 0; jj < 4; jj++) {
                int j = tx + 16*jj;
                SB[i*SSB + (j - i + 63)] = p[ii][jj];
            }
        }
        __syncthreads();

        // ---- accv += P @ V  (outer product, vector along d = tx*4) ----
        for (int k = 0; k < 64; k++) {
            float a0 = Pn[(ty     )*SK + k];
            float a1 = Pn[(ty + 16)*SK + k];
            float a2 = Pn[(ty + 32)*SK + k];
            float a3 = Pn[(ty + 48)*SK + k];
            float4 vv = *(const float4*)&Vs[k*SK + (tx << 2)];
            accv[0][0] += a0*vv.x; accv[0][1] += a0*vv.y; accv[0][2] += a0*vv.z; accv[0][3] += a0*vv.w;
            accv[1][0] += a1*vv.x; accv[1][1] += a1*vv.y; accv[1][2] += a1*vv.z; accv[1][3] += a1*vv.w;
            accv[2][0] += a2*vv.x; accv[2][1] += a2*vv.y; accv[2][2] += a2*vv.z; accv[2][3] += a2*vv.w;
            accv[3][0] += a3*vv.x; accv[3][1] += a3*vv.y; accv[3][2] += a3*vv.z; accv[3][3] += a3*vv.w;
        }
        // ---- accv += Pband @ Tvw ----
        for (int j = 0; j < 128; j++) {
            float a0 = SB[(ty     )*SSB + j];
            float a1 = SB[(ty + 16)*SSB + j];
            float a2 = SB[(ty + 32)*SSB + j];
            float a3 = SB[(ty + 48)*SSB + j];
            float4 tv = *(const float4*)&Tvw[j*SK + (tx << 2)];
            accv[0][0] += a0*tv.x; accv[0][1] += a0*tv.y; accv[0][2] += a0*tv.z; accv[0][3] += a0*tv.w;
            accv[1][0] += a1*tv.x; accv[1][1] += a1*tv.y; accv[1][2] += a1*tv.z; accv[1][3] += a1*tv.w;
            accv[2][0] += a2*tv.x; accv[2][1] += a2*tv.y; accv[2][2] += a2*tv.z; accv[2][3] += a2*tv.w;
            accv[3][0] += a3*tv.x; accv[3][1] += a3*tv.y; accv[3][2] += a3*tv.z; accv[3][3] += a3*tv.w;
        }
        __syncthreads();
    }

    // ---- epilogue: normalize and store ctx ----
    #pragma unroll
    for (int ii = 0; ii < 4; ii++) {
        float ls = lrow[ii];
        #pragma unroll
        for (int o = 1; o < 16; o <<= 1)
            ls += __shfl_xor_sync(0xffffffffu, ls, o);
        float inv = 1.0f / ls;
        int i = ty + 16*ii;
        float4 o4 = make_float4(accv[ii][0]*inv, accv[ii][1]*inv,
                                accv[ii][2]*inv, accv[ii][3]*inv);
        *(float4*)(g_ctx + (((size_t)(b*LL + q0 + i)*HH + h) << 6) + (tx << 2)) = o4;
    }
}

// ---------------------------------------------------------------------------
// Final FC: out[r, n] = sum_e ctx[r, e] * Wfc[n, e] + bfc[n]
// r in [0, 4096), n in [0, 1024), K = 1024. grid (64, 16).
// ---------------------------------------------------------------------------
__global__ __launch_bounds__(256) void fc_kernel(
    const float* __restrict__ Wfc, const float* __restrict__ bfc, float* __restrict__ out)
{
    __shared__ float Xs[64*SK];
    __shared__ float Ws[64*SK];

    const int tid = threadIdx.x;
    const int ty = tid >> 4, tx = tid & 15;
    const size_t r0 = (size_t)blockIdx.x * 64;
    const size_t n0 = (size_t)blockIdx.y * 64;

    float acc[4][4] = {};
    for (int e0 = 0; e0 < EMBN; e0 += 64) {
        #pragma unroll
        for (int t = 0; t < 4; t++) {
            int idx = tid + t*256;
            int rr = idx >> 4, cc = (idx & 15) << 2;
            *(float4*)&Xs[rr*SK + cc] = *(const float4*)(g_ctx + (r0 + rr)*EMBN + e0 + cc);
            *(float4*)&Ws[rr*SK + cc] = *(const float4*)(Wfc   + (n0 + rr)*EMBN + e0 + cc);
        }
        __syncthreads();
        for (int e = 0; e < 64; e += 4) {
            float4 a[4], bb[4];
            #pragma unroll
            for (int ii = 0; ii < 4; ii++) a[ii]  = *(const float4*)&Xs[(ty + 16*ii)*SK + e];
            #pragma unroll
            for (int jj = 0; jj < 4; jj++) bb[jj] = *(const float4*)&Ws[(tx + 16*jj)*SK + e];
            #pragma unroll
            for (int ii = 0; ii < 4; ii++)
                #pragma unroll
                for (int jj = 0; jj < 4; jj++)
                    acc[ii][jj] += a[ii].x*bb[jj].x + a[ii].y*bb[jj].y
                                 + a[ii].z*bb[jj].z + a[ii].w*bb[jj].w;
        }
        __syncthreads();
    }
    #pragma unroll
    for (int ii = 0; ii < 4; ii++) {
        size_t i = r0 + ty + 16*ii;
        #pragma unroll
        for (int jj = 0; jj < 4; jj++) {
            size_t n = n0 + tx + 16*jj;
            out[i*EMBN + n] = acc[ii][jj] + bfc[n];
        }
    }
}

// ---------------------------------------------------------------------------
extern "C" void kernel_launch(void* const* d_in, const int* in_sizes, int n_in,
                              void* d_out, int out_size)
{
    const float* query = (const float*)d_in[0];
    const float* key_  = (const float*)d_in[1];
    const float* value = (const float*)d_in[2];
    const int*   mask  = (const int*)d_in[3];
    const float* Wq = (const float*)d_in[4];
    const float* bq = (const float*)d_in[5];
    const float* Wk = (const float*)d_in[6];
    const float* bk = (const float*)d_in[7];
    const float* Wv = (const float*)d_in[8];
    const float* bv = (const float*)d_in[9];
    const float* Wfc = (const float*)d_in[10];
    const float* bfc = (const float*)d_in[11];
    const float* relk = (const float*)d_in[12];
    const float* relv = (const float*)d_in[13];
    float* out = (float*)d_out;

    cudaFuncSetAttribute(attn_kernel, cudaFuncAttributeMaxDynamicSharedMemorySize, ATT_SMEM_BYTES);

    proj_kernel<<<dim3(1024, 3, 1), 256>>>(query, key_, value, Wq, bq, Wk, bk, Wv, bv);
    attn_kernel<<<dim3(16, 16, 4), 256, ATT_SMEM_BYTES>>>(mask, relk, relv);
    fc_kernel<<<dim3(64, 16, 1), 256>>>(Wfc, bfc, out);
}

// round 2
// speedup vs baseline: 2.0538x; 2.0538x over previous
#include <cuda_runtime.h>
#include <cstdint>
#include <cstddef>

#define BB   4
#define LL   1024
#define HH   16
#define DD   64
#define EMBN 1024
#define MAXREL 512

#define SA  68     // stride for 64-wide tiles  (68 % 32 == 4 -> conflict-free frags)
#define SBD 132    // stride for 128-wide tiles (132 % 32 == 4)

// Scratch (allocation-free rule: device globals)
__device__ float g_q[BB*LL*HH*DD];
__device__ float g_k[BB*LL*HH*DD];
__device__ float g_v[BB*LL*HH*DD];
__device__ float g_ctx[BB*LL*HH*DD];

// ---------------------------------------------------------------------------
// helpers
// ---------------------------------------------------------------------------
__device__ __forceinline__ float tf32r(float x) {
    uint32_t u;
    asm("cvt.rn.tf32.f32 %0, %1;" : "=r"(u) : "f"(x));
    return __uint_as_float(u);
}

#define MMA_TF32(d0,d1,d2,d3,a0,a1,a2,a3,b0,b1)                              \
    asm volatile("mma.sync.aligned.m16n8k8.row.col.f32.tf32.tf32.f32 "       \
                 "{%0,%1,%2,%3}, {%4,%5,%6,%7}, {%8,%9}, {%0,%1,%2,%3};"     \
                 : "+f"(d0), "+f"(d1), "+f"(d2), "+f"(d3)                    \
                 : "r"(a0), "r"(a1), "r"(a2), "r"(a3), "r"(b0), "r"(b1))

// ---------------------------------------------------------------------------
// Projection: out[r, d] = sum_e X[r, e] * W[d, e] + b[d]   (unchanged, 52us)
// ---------------------------------------------------------------------------
__global__ __launch_bounds__(256) void proj_kernel(
    const float* __restrict__ query, const float* __restrict__ key_, const float* __restrict__ value,
    const float* __restrict__ Wq, const float* __restrict__ bq,
    const float* __restrict__ Wk, const float* __restrict__ bk,
    const float* __restrict__ Wv, const float* __restrict__ bv)
{
    __shared__ float Xs[64*SA];
    __shared__ float Ws[64*SA];
    __shared__ float bs[64];

    const float* X; const float* W; const float* bias; float* out;
    if (blockIdx.y == 0)      { X = query; W = Wq; bias = bq; out = g_q; }
    else if (blockIdx.y == 1) { X = key_;  W = Wk; bias = bk; out = g_k; }
    else                      { X = value; W = Wv; bias = bv; out = g_v; }

    const int tid = threadIdx.x;
    const size_t r0 = (size_t)blockIdx.x * 64;

    #pragma unroll
    for (int t = 0; t < 4; t++) {
        int idx = tid + t*256;
        int rr = idx >> 4, cc = (idx & 15) << 2;
        *(float4*)&Xs[rr*SA + cc] = *(const float4*)(X + (r0 + rr)*64 + cc);
        *(float4*)&Ws[rr*SA + cc] = *(const float4*)(W + (size_t)rr*64 + cc);
    }
    if (tid < 64) bs[tid] = bias[tid];
    __syncthreads();

    const int ty = tid >> 4, tx = tid & 15;
    float acc[4][4] = {};
    for (int e = 0; e < 64; e += 4) {
        float4 a[4], bb[4];
        #pragma unroll
        for (int ii = 0; ii < 4; ii++) a[ii]  = *(const float4*)&Xs[(ty + 16*ii)*SA + e];
        #pragma unroll
        for (int jj = 0; jj < 4; jj++) bb[jj] = *(const float4*)&Ws[(tx + 16*jj)*SA + e];
        #pragma unroll
        for (int ii = 0; ii < 4; ii++)
            #pragma unroll
            for (int jj = 0; jj < 4; jj++)
                acc[ii][jj] += a[ii].x*bb[jj].x + a[ii].y*bb[jj].y
                             + a[ii].z*bb[jj].z + a[ii].w*bb[jj].w;
    }
    #pragma unroll
    for (int ii = 0; ii < 4; ii++) {
        int i = ty + 16*ii;
        #pragma unroll
        for (int jj = 0; jj < 4; jj++) {
            int d = tx + 16*jj;
            out[(r0 + i)*64 + d] = acc[ii][jj] + bs[d];
        }
    }
}

// ---------------------------------------------------------------------------
// Flash attention with relative-position K/V bias — tf32 mma.sync version.
// One block per (q-block of 64, head, batch). 256 threads = 8 warps (4x2).
// ---------------------------------------------------------------------------
#define ATT_SMEM_WORDS (5*64*SA + 128*SA + 2*64*SBD + 192)
#define ATT_SMEM_BYTES (ATT_SMEM_WORDS * 4)

__global__ __launch_bounds__(256) void attn_kernel(
    const int*   __restrict__ mask,
    const float* __restrict__ relk,
    const float* __restrict__ relv)
{
    extern __shared__ float sm[];
    float* Qs    = sm;                 // 64 x SA   (tf32 Q)
    float* Ks    = Qs    + 64*SA;      // 64 x SA   [kpos][e]
    float* Vt    = Ks    + 64*SA;      // 64 x SA   [d][kpos]  (transposed V)
    float* Pn    = Vt    + 64*SA;      // 64 x SA   probabilities [q][kpos]
    float* SQK   = Pn    + 64*SA;      // 64 x SA   qk scores
    float* Tkw   = SQK   + 64*SA;      // 128 x SA  [j][e]  rel_k window
    float* Tvwt  = Tkw   + 128*SA;     // 64 x SBD  [d][j]  rel_v window transposed
    float* SBand = Tvwt  + 64*SBD;     // 64 x SBD  Srel scores, then band probs
    float* mrowS = SBand + 64*SBD;     // 64
    float* lrowS = mrowS + 64;         // 64
    float* cscS  = lrowS + 64;         // 64

    const int b  = blockIdx.z;
    const int h  = blockIdx.y;
    const int q0 = blockIdx.x * 64;
    const int tid  = threadIdx.x;
    const int warp = tid >> 5, lane = tid & 31;
    const int g = lane >> 2, t = lane & 3;       // mma quad coords
    const int wr = warp >> 1, wc = warp & 1;     // 4x2 warp grid
    const int ty = tid >> 4, tx = tid & 15;      // softmax coords

    if (tid < 64) { mrowS[tid] = -1e30f; lrowS[tid] = 0.0f; }

    // stage Q (tf32-rounded)
    #pragma unroll
    for (int tt = 0; tt < 4; tt++) {
        int idx = tid + tt*256;
        int rr = idx >> 4, cc = (idx & 15) << 2;
        float4 v = *(const float4*)(g_q + (((size_t)((b*LL + q0 + rr)*HH + h)) << 6) + cc);
        float4 w = make_float4(tf32r(v.x), tf32r(v.y), tf32r(v.z), tf32r(v.w));
        *(float4*)&Qs[rr*SA + cc] = w;
    }
    __syncthreads();

    // Q fragments held in registers for the whole CTA
    uint32_t qa[8][4];
    {
        const int r0 = wr*16 + g;
        #pragma unroll
        for (int ks = 0; ks < 8; ks++) {
            qa[ks][0] = __float_as_uint(Qs[r0*SA + ks*8 + t]);
            qa[ks][1] = __float_as_uint(Qs[(r0+8)*SA + ks*8 + t]);
            qa[ks][2] = __float_as_uint(Qs[r0*SA + ks*8 + t + 4]);
            qa[ks][3] = __float_as_uint(Qs[(r0+8)*SA + ks*8 + t + 4]);
        }
    }

    float oacc[4][4] = {};   // output fragments: n = wc*32 + nt*8

    for (int kt = 0; kt < 16; kt++) {
        const int k0 = kt * 64;
        const int d0 = k0 - q0;

        // ------------------ stage K / Tkw (row-major) ------------------
        #pragma unroll
        for (int tt = 0; tt < 4; tt++) {
            int idx = tid + tt*256;
            int rr = idx >> 4, cc = (idx & 15) << 2;
            float4 v = *(const float4*)(g_k + (((size_t)((b*LL + k0 + rr)*HH + h)) << 6) + cc);
            *(float4*)&Ks[rr*SA + cc] =
                make_float4(tf32r(v.x), tf32r(v.y), tf32r(v.z), tf32r(v.w));
        }
        #pragma unroll
        for (int tt = 0; tt < 8; tt++) {
            int idx = tid + tt*256;
            int rr = idx >> 4, cc = (idx & 15) << 2;
            int diff = d0 + rr - 63;
            diff = diff < -MAXREL ? -MAXREL : (diff > MAXREL ? MAXREL : diff);
            float4 v = *(const float4*)(relk + ((size_t)(diff + MAXREL) << 6) + cc);
            *(float4*)&Tkw[rr*SA + cc] =
                make_float4(tf32r(v.x), tf32r(v.y), tf32r(v.z), tf32r(v.w));
        }
        // ------------------ stage V transposed ------------------
        {
            int kp = tid & 63, dg = tid >> 6;           // kp: 0..63, dg: 0..3
            const float* src = g_v + (((size_t)((b*LL + k0 + kp)*HH + h)) << 6);
            #pragma unroll
            for (int j = 0; j < 4; j++) {
                int d = dg*16 + j*4;
                float4 v = *(const float4*)(src + d);
                Vt[(d+0)*SA + kp] = tf32r(v.x);
                Vt[(d+1)*SA + kp] = tf32r(v.y);
                Vt[(d+2)*SA + kp] = tf32r(v.z);
                Vt[(d+3)*SA + kp] = tf32r(v.w);
            }
        }
        // ------------------ stage relV transposed ------------------
        {
            int jj = tid & 127, dg = tid >> 7;          // jj: 0..127, dg: 0..1
            int diff = d0 + jj - 63;
            diff = diff < -MAXREL ? -MAXREL : (diff > MAXREL ? MAXREL : diff);
            const float* src = relv + ((size_t)(diff + MAXREL) << 6);
            #pragma unroll
            for (int j = 0; j < 8; j++) {
                int d = dg*32 + j*4;
                float4 v = *(const float4*)(src + d);
                Tvwt[(d+0)*SBD + jj] = tf32r(v.x);
                Tvwt[(d+1)*SBD + jj] = tf32r(v.y);
                Tvwt[(d+2)*SBD + jj] = tf32r(v.z);
                Tvwt[(d+3)*SBD + jj] = tf32r(v.w);
            }
        }
        __syncthreads();

        // ------------------ GEMM1: S[64x192] = Q x [K | Tkw]^T ------------------
        {
            const int r0 = wr*16 + g;
            #pragma unroll
            for (int nt = 0; nt < 12; nt++) {
                const int n0 = wc*96 + nt*8;
                const float* Bb = (n0 < 64) ? (Ks + (n0 + g)*SA)
                                            : (Tkw + (n0 - 64 + g)*SA);
                float c0 = 0.f, c1 = 0.f, c2 = 0.f, c3 = 0.f;
                #pragma unroll
                for (int ks = 0; ks < 8; ks++) {
                    uint32_t b0 = __float_as_uint(Bb[ks*8 + t]);
                    uint32_t b1 = __float_as_uint(Bb[ks*8 + t + 4]);
                    MMA_TF32(c0, c1, c2, c3,
                             qa[ks][0], qa[ks][1], qa[ks][2], qa[ks][3], b0, b1);
                }
                if (n0 < 64) {
                    int cb = n0 + 2*t;
                    *(float2*)&SQK[r0*SA + cb]     = make_float2(c0, c1);
                    *(float2*)&SQK[(r0+8)*SA + cb] = make_float2(c2, c3);
                } else {
                    int cb = n0 - 64 + 2*t;
                    *(float2*)&SBand[r0*SBD + cb]     = make_float2(c0, c1);
                    *(float2*)&SBand[(r0+8)*SBD + cb] = make_float2(c2, c3);
                }
            }
        }
        __syncthreads();

        // ------------------ softmax (scalar layout) ------------------
        float p[4][4];
        #pragma unroll
        for (int ii = 0; ii < 4; ii++) {
            const int r = ty + 16*ii;
            float4 s4 = *(const float4*)&SQK[r*SA + 4*tx];
            int4  m4  = *(const int4*)(mask + ((size_t)b*LL + q0 + r)*LL + k0 + 4*tx);
            float sv[4];
            sv[0] = m4.x ? s4.x : -1e20f;
            sv[1] = m4.y ? s4.y : -1e20f;
            sv[2] = m4.z ? s4.z : -1e20f;
            sv[3] = m4.w ? s4.w : -1e20f;
            #pragma unroll
            for (int cc = 0; cc < 4; cc++) {
                int c = 4*tx + cc;
                sv[cc] = (sv[cc] + SBand[r*SBD + c - r + 63]) * 0.125f;
            }
            float rm = fmaxf(fmaxf(sv[0], sv[1]), fmaxf(sv[2], sv[3]));
            #pragma unroll
            for (int o = 1; o < 16; o <<= 1)
                rm = fmaxf(rm, __shfl_xor_sync(0xffffffffu, rm, o));
            float mold = mrowS[r];
            float mn = fmaxf(mold, rm);
            float csc = __expf(mold - mn);
            float ls = 0.f;
            #pragma unroll
            for (int cc = 0; cc < 4; cc++) {
                p[ii][cc] = __expf(sv[cc] - mn);
                ls += p[ii][cc];
            }
            #pragma unroll
            for (int o = 1; o < 16; o <<= 1)
                ls += __shfl_xor_sync(0xffffffffu, ls, o);
            if (tx == 0) {
                mrowS[r] = mn;
                cscS[r]  = csc;
                lrowS[r] = lrowS[r]*csc + ls;
            }
            // probabilities (tf32-rounded) for the PV mma
            *(float4*)&Pn[r*SA + 4*tx] = make_float4(
                tf32r(p[ii][0]), tf32r(p[ii][1]), tf32r(p[ii][2]), tf32r(p[ii][3]));
        }
        __syncthreads();

        // zero the band buffer, then scatter probabilities into band positions
        for (int i2 = tid; i2 < 64*SBD; i2 += 256) SBand[i2] = 0.0f;
        __syncthreads();
        #pragma unroll
        for (int ii = 0; ii < 4; ii++) {
            const int r = ty + 16*ii;
            #pragma unroll
            for (int cc = 0; cc < 4; cc++) {
                int c = 4*tx + cc;
                SBand[r*SBD + c - r + 63] = tf32r(p[ii][cc]);
            }
        }
        __syncthreads();

        // ------------------ GEMM2: oacc = csc*oacc + P@V + Pband@Tvw ------------------
        {
            const int r0 = wr*16 + g;
            const float f0 = cscS[r0], f1 = cscS[r0+8];
            #pragma unroll
            for (int nt = 0; nt < 4; nt++) {
                oacc[nt][0] *= f0; oacc[nt][1] *= f0;
                oacc[nt][2] *= f1; oacc[nt][3] *= f1;
            }
            // P @ V
            #pragma unroll
            for (int ks = 0; ks < 8; ks++) {
                uint32_t a0 = __float_as_uint(Pn[r0*SA + ks*8 + t]);
                uint32_t a1 = __float_as_uint(Pn[(r0+8)*SA + ks*8 + t]);
                uint32_t a2 = __float_as_uint(Pn[r0*SA + ks*8 + t + 4]);
                uint32_t a3 = __float_as_uint(Pn[(r0+8)*SA + ks*8 + t + 4]);
                #pragma unroll
                for (int nt = 0; nt < 4; nt++) {
                    const float* Bb = Vt + (wc*32 + nt*8 + g)*SA;
                    uint32_t b0 = __float_as_uint(Bb[ks*8 + t]);
                    uint32_t b1 = __float_as_uint(Bb[ks*8 + t + 4]);
                    MMA_TF32(oacc[nt][0], oacc[nt][1], oacc[nt][2], oacc[nt][3],
                             a0, a1, a2, a3, b0, b1);
                }
            }
            // Pband @ Tvw
            #pragma unroll
            for (int ks = 0; ks < 16; ks++) {
                uint32_t a0 = __float_as_uint(SBand[r0*SBD + ks*8 + t]);
                uint32_t a1 = __float_as_uint(SBand[(r0+8)*SBD + ks*8 + t]);
                uint32_t a2 = __float_as_uint(SBand[r0*SBD + ks*8 + t + 4]);
                uint32_t a3 = __float_as_uint(SBand[(r0+8)*SBD + ks*8 + t + 4]);
                #pragma unroll
                for (int nt = 0; nt < 4; nt++) {
                    const float* Bb = Tvwt + (wc*32 + nt*8 + g)*SBD;
                    uint32_t b0 = __float_as_uint(Bb[ks*8 + t]);
                    uint32_t b1 = __float_as_uint(Bb[ks*8 + t + 4]);
                    MMA_TF32(oacc[nt][0], oacc[nt][1], oacc[nt][2], oacc[nt][3],
                             a0, a1, a2, a3, b0, b1);
                }
            }
        }
        __syncthreads();
    }

    // ------------------ epilogue: normalize, store ctx ------------------
    {
        const int r0 = wr*16 + g;
        const float l0 = 1.0f / lrowS[r0];
        const float l1 = 1.0f / lrowS[r0 + 8];
        const size_t base0 = (((size_t)((b*LL + q0 + r0    )*HH + h)) << 6);
        const size_t base1 = (((size_t)((b*LL + q0 + r0 + 8)*HH + h)) << 6);
        #pragma unroll
        for (int nt = 0; nt < 4; nt++) {
            int c = wc*32 + nt*8 + 2*t;
            *(float2*)(g_ctx + base0 + c) = make_float2(oacc[nt][0]*l0, oacc[nt][1]*l0);
            *(float2*)(g_ctx + base1 + c) = make_float2(oacc[nt][2]*l1, oacc[nt][3]*l1);
        }
    }
}

// ---------------------------------------------------------------------------
// Final FC via tf32 mma: out[r, n] = sum_e ctx[r, e] * Wfc[n, e] + bfc[n]
// grid (64, 16), 256 threads = 8 warps (4x2), 64x64 tile, K = 1024.
// ---------------------------------------------------------------------------
__global__ __launch_bounds__(256) void fc_kernel(
    const float* __restrict__ Wfc, const float* __restrict__ bfc, float* __restrict__ out)
{
    __shared__ float Xs[64*SA];
    __shared__ float Ws[64*SA];

    const int tid  = threadIdx.x;
    const int warp = tid >> 5, lane = tid & 31;
    const int g = lane >> 2, t = lane & 3;
    const int wr = warp >> 1, wc = warp & 1;
    const size_t r0 = (size_t)blockIdx.x * 64;
    const size_t n0 = (size_t)blockIdx.y * 64;

    float oacc[4][4] = {};

    for (int e0 = 0; e0 < EMBN; e0 += 64) {
        #pragma unroll
        for (int tt = 0; tt < 4; tt++) {
            int idx = tid + tt*256;
            int rr = idx >> 4, cc = (idx & 15) << 2;
            float4 a = *(const float4*)(g_ctx + (r0 + rr)*EMBN + e0 + cc);
            float4 w = *(const float4*)(Wfc   + (n0 + rr)*EMBN + e0 + cc);
            *(float4*)&Xs[rr*SA + cc] = make_float4(tf32r(a.x), tf32r(a.y), tf32r(a.z), tf32r(a.w));
            *(float4*)&Ws[rr*SA + cc] = make_float4(tf32r(w.x), tf32r(w.y), tf32r(w.z), tf32r(w.w));
        }
        __syncthreads();
        {
            const int rr0 = wr*16 + g;
            #pragma unroll
            for (int ks = 0; ks < 8; ks++) {
                uint32_t a0 = __float_as_uint(Xs[rr0*SA + ks*8 + t]);
                uint32_t a1 = __float_as_uint(Xs[(rr0+8)*SA + ks*8 + t]);
                uint32_t a2 = __float_as_uint(Xs[rr0*SA + ks*8 + t + 4]);
                uint32_t a3 = __float_as_uint(Xs[(rr0+8)*SA + ks*8 + t + 4]);
                #pragma unroll
                for (int nt = 0; nt < 4; nt++) {
                    const float* Bb = Ws + (wc*32 + nt*8 + g)*SA;
                    uint32_t b0 = __float_as_uint(Bb[ks*8 + t]);
                    uint32_t b1 = __float_as_uint(Bb[ks*8 + t + 4]);
                    MMA_TF32(oacc[nt][0], oacc[nt][1], oacc[nt][2], oacc[nt][3],
                             a0, a1, a2, a3, b0, b1);
                }
            }
        }
        __syncthreads();
    }

    {
        const int rr0 = wr*16 + g;
        #pragma unroll
        for (int nt = 0; nt < 4; nt++) {
            size_t c = n0 + wc*32 + nt*8 + 2*t;
            float bv0 = bfc[c], bv1 = bfc[c+1];
            *(float2*)(out + (r0 + rr0    )*EMBN + c) =
                make_float2(oacc[nt][0] + bv0, oacc[nt][1] + bv1);
            *(float2*)(out + (r0 + rr0 + 8)*EMBN + c) =
                make_float2(oacc[nt][2] + bv0, oacc[nt][3] + bv1);
        }
    }
}

// ---------------------------------------------------------------------------
extern "C" void kernel_launch(void* const* d_in, const int* in_sizes, int n_in,
                              void* d_out, int out_size)
{
    const float* query = (const float*)d_in[0];
    const float* key_  = (const float*)d_in[1];
    const float* value = (const float*)d_in[2];
    const int*   mask  = (const int*)d_in[3];
    const float* Wq = (const float*)d_in[4];
    const float* bq = (const float*)d_in[5];
    const float* Wk = (const float*)d_in[6];
    const float* bk = (const float*)d_in[7];
    const float* Wv = (const float*)d_in[8];
    const float* bv = (const float*)d_in[9];
    const float* Wfc = (const float*)d_in[10];
    const float* bfc = (const float*)d_in[11];
    const float* relk = (const float*)d_in[12];
    const float* relv = (const float*)d_in[13];
    float* out = (float*)d_out;

    cudaFuncSetAttribute(attn_kernel, cudaFuncAttributeMaxDynamicSharedMemorySize, ATT_SMEM_BYTES);

    proj_kernel<<<dim3(1024, 3, 1), 256>>>(query, key_, value, Wq, bq, Wk, bk, Wv, bv);
    attn_kernel<<<dim3(16, 16, 4), 256, ATT_SMEM_BYTES>>>(mask, relk, relv);
    fc_kernel<<<dim3(64, 16, 1), 256>>>(Wfc, bfc, out);
}

// round 3
// speedup vs baseline: 2.5043x; 1.2194x over previous
#include <cuda_runtime.h>
#include <cuda_fp16.h>
#include <cstdint>
#include <cstddef>

#define BB   4
#define LL   1024
#define HH   16
#define DD   64
#define EMBN 1024
#define MAXREL 512

#define SH   72    // half stride, 64-wide tiles  (72/2 = 36 == 4 mod 32 -> conflict-free)
#define SH2  136   // half stride, 128-wide tiles (68 == 4 mod 32)
#define SF   132   // float stride for SrelF
#define SQ   68    // float stride for SQK

// Scratch (allocation-free rule: device globals)
__device__ float g_q[BB*LL*HH*DD];
__device__ float g_k[BB*LL*HH*DD];
__device__ float g_v[BB*LL*HH*DD];
__device__ float g_ctx[BB*LL*HH*DD];

// ---------------------------------------------------------------------------
#define MMA_F16(d0,d1,d2,d3,a0,a1,a2,a3,b0,b1)                               \
    asm volatile("mma.sync.aligned.m16n8k16.row.col.f32.f16.f16.f32 "        \
                 "{%0,%1,%2,%3}, {%4,%5,%6,%7}, {%8,%9}, {%0,%1,%2,%3};"     \
                 : "+f"(d0), "+f"(d1), "+f"(d2), "+f"(d3)                    \
                 : "r"(a0), "r"(a1), "r"(a2), "r"(a3), "r"(b0), "r"(b1))

__device__ __forceinline__ uint2 f4_to_h4(float4 v) {
    __half2 h0 = __floats2half2_rn(v.x, v.y);
    __half2 h1 = __floats2half2_rn(v.z, v.w);
    uint2 r;
    r.x = *(uint32_t*)&h0;
    r.y = *(uint32_t*)&h1;
    return r;
}
__device__ __forceinline__ uint32_t ldh2(const __half* p) {
    return *(const uint32_t*)p;
}

// ---------------------------------------------------------------------------
// Projection (unchanged fma version, 52us): out[r,d] = X[r,:] . W[d,:] + b[d]
// ---------------------------------------------------------------------------
#define SA 68
__global__ __launch_bounds__(256) void proj_kernel(
    const float* __restrict__ query, const float* __restrict__ key_, const float* __restrict__ value,
    const float* __restrict__ Wq, const float* __restrict__ bq,
    const float* __restrict__ Wk, const float* __restrict__ bk,
    const float* __restrict__ Wv, const float* __restrict__ bv)
{
    __shared__ float Xs[64*SA];
    __shared__ float Ws[64*SA];
    __shared__ float bs[64];

    const float* X; const float* W; const float* bias; float* out;
    if (blockIdx.y == 0)      { X = query; W = Wq; bias = bq; out = g_q; }
    else if (blockIdx.y == 1) { X = key_;  W = Wk; bias = bk; out = g_k; }
    else                      { X = value; W = Wv; bias = bv; out = g_v; }

    const int tid = threadIdx.x;
    const size_t r0 = (size_t)blockIdx.x * 64;

    #pragma unroll
    for (int t = 0; t < 4; t++) {
        int idx = tid + t*256;
        int rr = idx >> 4, cc = (idx & 15) << 2;
        *(float4*)&Xs[rr*SA + cc] = *(const float4*)(X + (r0 + rr)*64 + cc);
        *(float4*)&Ws[rr*SA + cc] = *(const float4*)(W + (size_t)rr*64 + cc);
    }
    if (tid < 64) bs[tid] = bias[tid];
    __syncthreads();

    const int ty = tid >> 4, tx = tid & 15;
    float acc[4][4] = {};
    for (int e = 0; e < 64; e += 4) {
        float4 a[4], bb[4];
        #pragma unroll
        for (int ii = 0; ii < 4; ii++) a[ii]  = *(const float4*)&Xs[(ty + 16*ii)*SA + e];
        #pragma unroll
        for (int jj = 0; jj < 4; jj++) bb[jj] = *(const float4*)&Ws[(tx + 16*jj)*SA + e];
        #pragma unroll
        for (int ii = 0; ii < 4; ii++)
            #pragma unroll
            for (int jj = 0; jj < 4; jj++)
                acc[ii][jj] += a[ii].x*bb[jj].x + a[ii].y*bb[jj].y
                             + a[ii].z*bb[jj].z + a[ii].w*bb[jj].w;
    }
    #pragma unroll
    for (int ii = 0; ii < 4; ii++) {
        int i = ty + 16*ii;
        #pragma unroll
        for (int jj = 0; jj < 4; jj++) {
            int d = tx + 16*jj;
            out[(r0 + i)*64 + d] = acc[ii][jj] + bs[d];
        }
    }
}

// ---------------------------------------------------------------------------
// Flash attention + relative bias, fp16 m16n8k16, rolling rel window.
// One block per (q-block 64, head, batch). 256 threads = 8 warps (4x2).
// ---------------------------------------------------------------------------
#define ATT_F_WORDS (64*SQ + 64*SF + 192)
#define ATT_H_WORDS (4*64*SH + 128*SH + 2*64*SH2)
#define ATT_SMEM_BYTES (ATT_F_WORDS*4 + ATT_H_WORDS*2)

__global__ __launch_bounds__(256) void attn_kernel(
    const int*   __restrict__ mask,
    const float* __restrict__ relk,
    const float* __restrict__ relv)
{
    extern __shared__ float smf[];
    float*  SQK   = smf;                      // 64 x SQ   (QK scores)
    float*  SrelF = SQK   + 64*SQ;            // 64 x SF   (rel scores, 128-col ring)
    float*  mrowS = SrelF + 64*SF;            // 64
    float*  lrowS = mrowS + 64;               // 64
    float*  cscS  = lrowS + 64;               // 64
    __half* Qh    = (__half*)(cscS + 64);     // 64 x SH
    __half* Kh    = Qh   + 64*SH;             // 64 x SH   [kpos][e]
    __half* Vt    = Kh   + 64*SH;             // 64 x SH   [d][kpos]
    __half* Ph    = Vt   + 64*SH;             // 64 x SH   probs [q][kpos]
    __half* Tkw   = Ph   + 64*SH;             // 128 x SH  rel_k ring [phys][e]
    __half* Tvwt  = Tkw  + 128*SH;            // 64 x SH2  rel_v ring [d][phys]
    __half* Bnd   = Tvwt + 64*SH2;            // 64 x SH2  band probs [q][phys]

    const int b  = blockIdx.z;
    const int h  = blockIdx.y;
    const int q0 = blockIdx.x * 64;
    const int tid  = threadIdx.x;
    const int warp = tid >> 5, lane = tid & 31;
    const int g = lane >> 2, t = lane & 3;
    const int wr = warp >> 1, wc = warp & 1;
    const int ty = tid >> 4, tx = tid & 15;
    const int r0 = wr*16 + g;

    if (tid < 64) { mrowS[tid] = -1e30f; lrowS[tid] = 0.0f; }
    // zero band buffer once
    for (int i = tid; i < 64*SH2/2; i += 256) ((uint32_t*)Bnd)[i] = 0u;

    // stage Q (half)
    #pragma unroll
    for (int tt = 0; tt < 4; tt++) {
        int idx = tid + tt*256;
        int rr = idx >> 4, cc = (idx & 15) << 2;
        float4 v = *(const float4*)(g_q + (((size_t)((b*LL + q0 + rr)*HH + h)) << 6) + cc);
        *(uint2*)&Qh[rr*SH + cc] = f4_to_h4(v);
    }
    __syncthreads();

    // Q A-fragments in registers for whole kernel (K=64 -> 4 ks steps)
    uint32_t qa[4][4];
    #pragma unroll
    for (int ks = 0; ks < 4; ks++) {
        qa[ks][0] = ldh2(&Qh[ r0    *SH + ks*16 + 2*t    ]);
        qa[ks][1] = ldh2(&Qh[(r0+8) *SH + ks*16 + 2*t    ]);
        qa[ks][2] = ldh2(&Qh[ r0    *SH + ks*16 + 2*t + 8]);
        qa[ks][3] = ldh2(&Qh[(r0+8) *SH + ks*16 + 2*t + 8]);
    }

    float oacc[4][4] = {};

    for (int kt = 0; kt < 16; kt++) {
        const int k0 = kt * 64;
        const int d0 = k0 - q0;
        const int pb = ((kt + 1) & 1) << 6;   // phys base of the NEW rel block
        const int kb = (kt & 1) << 6;         // ring rotation for lookups this tile

        // ---- clear previous tile's band entries ----
        if (kt > 0) {
            const int kbp = ((kt - 1) & 1) << 6;
            const __half hz = __float2half_rn(0.0f);
            #pragma unroll
            for (int ii = 0; ii < 4; ii++) {
                int r = ty + 16*ii;
                #pragma unroll
                for (int cc = 0; cc < 4; cc++) {
                    int c = 4*tx + cc;
                    Bnd[r*SH2 + ((c - r + 63 + kbp) & 127)] = hz;
                }
            }
        }

        // ---- stage K (half) ----
        #pragma unroll
        for (int tt = 0; tt < 4; tt++) {
            int idx = tid + tt*256;
            int rr = idx >> 4, cc = (idx & 15) << 2;
            float4 v = *(const float4*)(g_k + (((size_t)((b*LL + k0 + rr)*HH + h)) << 6) + cc);
            *(uint2*)&Kh[rr*SH + cc] = f4_to_h4(v);
        }
        // ---- stage V transposed (half) ----
        {
            int kp = tid & 63, dg = tid >> 6;
            const float* src = g_v + (((size_t)((b*LL + k0 + kp)*HH + h)) << 6);
            #pragma unroll
            for (int j = 0; j < 4; j++) {
                int d = dg*16 + j*4;
                float4 v = *(const float4*)(src + d);
                Vt[(d+0)*SH + kp] = __float2half_rn(v.x);
                Vt[(d+1)*SH + kp] = __float2half_rn(v.y);
                Vt[(d+2)*SH + kp] = __float2half_rn(v.z);
                Vt[(d+3)*SH + kp] = __float2half_rn(v.w);
            }
        }
        // ---- stage new rel blocks (Tkw rows, Tvwt cols) ----
        const int nblk = (kt == 0) ? 2 : 1;
        for (int blk = 0; blk < nblk; blk++) {
            const int pbX = (kt == 0) ? (blk << 6) : pb;
            const int jj0 = (kt == 0) ? (blk << 6) : 64;
            #pragma unroll
            for (int tt = 0; tt < 4; tt++) {
                int idx = tid + tt*256;
                int rloc = idx >> 4, cc = (idx & 15) << 2;
                int diff = d0 + jj0 + rloc - 63;
                diff = diff < -MAXREL ? -MAXREL : (diff > MAXREL ? MAXREL : diff);
                float4 v = *(const float4*)(relk + ((size_t)(diff + MAXREL) << 6) + cc);
                *(uint2*)&Tkw[(pbX + rloc)*SH + cc] = f4_to_h4(v);
            }
            {
                int jloc = tid & 63, dg = tid >> 6;
                int diff = d0 + jj0 + jloc - 63;
                diff = diff < -MAXREL ? -MAXREL : (diff > MAXREL ? MAXREL : diff);
                const float* src = relv + ((size_t)(diff + MAXREL) << 6);
                #pragma unroll
                for (int j = 0; j < 4; j++) {
                    int d = dg*16 + j*4;
                    float4 v = *(const float4*)(src + d);
                    Tvwt[(d+0)*SH2 + pbX + jloc] = __float2half_rn(v.x);
                    Tvwt[(d+1)*SH2 + pbX + jloc] = __float2half_rn(v.y);
                    Tvwt[(d+2)*SH2 + pbX + jloc] = __float2half_rn(v.z);
                    Tvwt[(d+3)*SH2 + pbX + jloc] = __float2half_rn(v.w);
                }
            }
        }
        __syncthreads();

        // ---- GEMM1a: QK scores ----
        #pragma unroll
        for (int nt = 0; nt < 4; nt++) {
            const int n0 = wc*32 + nt*8;
            const __half* Bb = Kh + (n0 + g)*SH;
            float c0 = 0.f, c1 = 0.f, c2 = 0.f, c3 = 0.f;
            #pragma unroll
            for (int ks = 0; ks < 4; ks++) {
                uint32_t b0 = ldh2(Bb + ks*16 + 2*t);
                uint32_t b1 = ldh2(Bb + ks*16 + 2*t + 8);
                MMA_F16(c0, c1, c2, c3, qa[ks][0], qa[ks][1], qa[ks][2], qa[ks][3], b0, b1);
            }
            *(float2*)&SQK[ r0   *SQ + n0 + 2*t] = make_float2(c0, c1);
            *(float2*)&SQK[(r0+8)*SQ + n0 + 2*t] = make_float2(c2, c3);
        }
        // ---- GEMM1b: rel scores for NEW block(s) ----
        for (int blk = 0; blk < nblk; blk++) {
            const int pbX = (kt == 0) ? (blk << 6) : pb;
            #pragma unroll
            for (int nt = 0; nt < 4; nt++) {
                const int nn = wc*32 + nt*8;
                const __half* Bb = Tkw + (pbX + nn + g)*SH;
                float c0 = 0.f, c1 = 0.f, c2 = 0.f, c3 = 0.f;
                #pragma unroll
                for (int ks = 0; ks < 4; ks++) {
                    uint32_t b0 = ldh2(Bb + ks*16 + 2*t);
                    uint32_t b1 = ldh2(Bb + ks*16 + 2*t + 8);
                    MMA_F16(c0, c1, c2, c3, qa[ks][0], qa[ks][1], qa[ks][2], qa[ks][3], b0, b1);
                }
                *(float2*)&SrelF[ r0   *SF + pbX + nn + 2*t] = make_float2(c0, c1);
                *(float2*)&SrelF[(r0+8)*SF + pbX + nn + 2*t] = make_float2(c2, c3);
            }
        }
        __syncthreads();

        // ---- softmax ----
        #pragma unroll
        for (int ii = 0; ii < 4; ii++) {
            const int r = ty + 16*ii;
            float4 s4 = *(const float4*)&SQK[r*SQ + 4*tx];
            int4  m4  = *(const int4*)(mask + ((size_t)b*LL + q0 + r)*LL + k0 + 4*tx);
            float sv[4];
            sv[0] = m4.x ? s4.x : -1e20f;
            sv[1] = m4.y ? s4.y : -1e20f;
            sv[2] = m4.z ? s4.z : -1e20f;
            sv[3] = m4.w ? s4.w : -1e20f;
            #pragma unroll
            for (int cc = 0; cc < 4; cc++) {
                int c = 4*tx + cc;
                sv[cc] = (sv[cc] + SrelF[r*SF + ((c - r + 63 + kb) & 127)]) * 0.125f;
            }
            float rm = fmaxf(fmaxf(sv[0], sv[1]), fmaxf(sv[2], sv[3]));
            #pragma unroll
            for (int o = 1; o < 16; o <<= 1)
                rm = fmaxf(rm, __shfl_xor_sync(0xffffffffu, rm, o));
            float mold = mrowS[r];
            float mn = fmaxf(mold, rm);
            float csc = __expf(mold - mn);
            float p[4], ls = 0.f;
            #pragma unroll
            for (int cc = 0; cc < 4; cc++) { p[cc] = __expf(sv[cc] - mn); ls += p[cc]; }
            #pragma unroll
            for (int o = 1; o < 16; o <<= 1)
                ls += __shfl_xor_sync(0xffffffffu, ls, o);
            if (tx == 0) {
                mrowS[r] = mn;
                cscS[r]  = csc;
                lrowS[r] = lrowS[r]*csc + ls;
            }
            // probs -> Ph (half), and scatter into band ring
            uint2 ph;
            {
                __half2 h0 = __floats2half2_rn(p[0], p[1]);
                __half2 h1 = __floats2half2_rn(p[2], p[3]);
                ph.x = *(uint32_t*)&h0; ph.y = *(uint32_t*)&h1;
            }
            *(uint2*)&Ph[r*SH + 4*tx] = ph;
            #pragma unroll
            for (int cc = 0; cc < 4; cc++) {
                int c = 4*tx + cc;
                Bnd[r*SH2 + ((c - r + 63 + kb) & 127)] = __float2half_rn(p[cc]);
            }
        }
        __syncthreads();

        // ---- GEMM2: oacc = csc*oacc + P@V + Pband@Tvw ----
        {
            const float f0 = cscS[r0], f1 = cscS[r0+8];
            #pragma unroll
            for (int nt = 0; nt < 4; nt++) {
                oacc[nt][0] *= f0; oacc[nt][1] *= f0;
                oacc[nt][2] *= f1; oacc[nt][3] *= f1;
            }
            // P @ V (K = 64)
            #pragma unroll
            for (int ks = 0; ks < 4; ks++) {
                uint32_t a0 = ldh2(&Ph[ r0   *SH + ks*16 + 2*t    ]);
                uint32_t a1 = ldh2(&Ph[(r0+8)*SH + ks*16 + 2*t    ]);
                uint32_t a2 = ldh2(&Ph[ r0   *SH + ks*16 + 2*t + 8]);
                uint32_t a3 = ldh2(&Ph[(r0+8)*SH + ks*16 + 2*t + 8]);
                #pragma unroll
                for (int nt = 0; nt < 4; nt++) {
                    const __half* Bb = Vt + (wc*32 + nt*8 + g)*SH;
                    uint32_t b0 = ldh2(Bb + ks*16 + 2*t);
                    uint32_t b1 = ldh2(Bb + ks*16 + 2*t + 8);
                    MMA_F16(oacc[nt][0], oacc[nt][1], oacc[nt][2], oacc[nt][3],
                            a0, a1, a2, a3, b0, b1);
                }
            }
            // Pband @ Tvw (K = 128)
            #pragma unroll
            for (int ks = 0; ks < 8; ks++) {
                uint32_t a0 = ldh2(&Bnd[ r0   *SH2 + ks*16 + 2*t    ]);
                uint32_t a1 = ldh2(&Bnd[(r0+8)*SH2 + ks*16 + 2*t    ]);
                uint32_t a2 = ldh2(&Bnd[ r0   *SH2 + ks*16 + 2*t + 8]);
                uint32_t a3 = ldh2(&Bnd[(r0+8)*SH2 + ks*16 + 2*t + 8]);
                #pragma unroll
                for (int nt = 0; nt < 4; nt++) {
                    const __half* Bb = Tvwt + (wc*32 + nt*8 + g)*SH2;
                    uint32_t b0 = ldh2(Bb + ks*16 + 2*t);
                    uint32_t b1 = ldh2(Bb + ks*16 + 2*t + 8);
                    MMA_F16(oacc[nt][0], oacc[nt][1], oacc[nt][2], oacc[nt][3],
                            a0, a1, a2, a3, b0, b1);
                }
            }
        }
        __syncthreads();
    }

    // ---- epilogue ----
    {
        const float l0 = 1.0f / lrowS[r0];
        const float l1 = 1.0f / lrowS[r0 + 8];
        const size_t base0 = (((size_t)((b*LL + q0 + r0    )*HH + h)) << 6);
        const size_t base1 = (((size_t)((b*LL + q0 + r0 + 8)*HH + h)) << 6);
        #pragma unroll
        for (int nt = 0; nt < 4; nt++) {
            int c = wc*32 + nt*8 + 2*t;
            *(float2*)(g_ctx + base0 + c) = make_float2(oacc[nt][0]*l0, oacc[nt][1]*l0);
            *(float2*)(g_ctx + base1 + c) = make_float2(oacc[nt][2]*l1, oacc[nt][3]*l1);
        }
    }
}

// ---------------------------------------------------------------------------
// Final FC, fp16 mma, 128x128 tiles. grid (32, 8), 256 threads (4x2 warps).
// ---------------------------------------------------------------------------
__global__ __launch_bounds__(256) void fc_kernel(
    const float* __restrict__ Wfc, const float* __restrict__ bfc, float* __restrict__ out)
{
    __shared__ __half Xs[128*SH];
    __shared__ __half Ws[128*SH];

    const int tid  = threadIdx.x;
    const int warp = tid >> 5, lane = tid & 31;
    const int g = lane >> 2, t = lane & 3;
    const int wr = warp >> 1, wc = warp & 1;
    const size_t r0 = (size_t)blockIdx.x * 128;
    const size_t n0 = (size_t)blockIdx.y * 128;

    float oacc[2][8][4] = {};

    for (int e0 = 0; e0 < EMBN; e0 += 64) {
        #pragma unroll
        for (int tt = 0; tt < 8; tt++) {
            int idx = tid + tt*256;
            int rr = idx >> 4, cc = (idx & 15) << 2;
            float4 a = *(const float4*)(g_ctx + (r0 + rr)*EMBN + e0 + cc);
            float4 w = *(const float4*)(Wfc   + (n0 + rr)*EMBN + e0 + cc);
            *(uint2*)&Xs[rr*SH + cc] = f4_to_h4(a);
            *(uint2*)&Ws[rr*SH + cc] = f4_to_h4(w);
        }
        __syncthreads();
        #pragma unroll
        for (int ks = 0; ks < 4; ks++) {
            uint32_t a[2][4];
            #pragma unroll
            for (int mi = 0; mi < 2; mi++) {
                int ar = wr*32 + mi*16 + g;
                a[mi][0] = ldh2(&Xs[ ar   *SH + ks*16 + 2*t    ]);
                a[mi][1] = ldh2(&Xs[(ar+8)*SH + ks*16 + 2*t    ]);
                a[mi][2] = ldh2(&Xs[ ar   *SH + ks*16 + 2*t + 8]);
                a[mi][3] = ldh2(&Xs[(ar+8)*SH + ks*16 + 2*t + 8]);
            }
            #pragma unroll
            for (int nt = 0; nt < 8; nt++) {
                const __half* Bb = Ws + (wc*64 + nt*8 + g)*SH;
                uint32_t b0 = ldh2(Bb + ks*16 + 2*t);
                uint32_t b1 = ldh2(Bb + ks*16 + 2*t + 8);
                #pragma unroll
                for (int mi = 0; mi < 2; mi++)
                    MMA_F16(oacc[mi][nt][0], oacc[mi][nt][1], oacc[mi][nt][2], oacc[mi][nt][3],
                            a[mi][0], a[mi][1], a[mi][2], a[mi][3], b0, b1);
            }
        }
        __syncthreads();
    }

    #pragma unroll
    for (int mi = 0; mi < 2; mi++) {
        size_t ra = r0 + wr*32 + mi*16 + g;
        #pragma unroll
        for (int nt = 0; nt < 8; nt++) {
            size_t c = n0 + wc*64 + nt*8 + 2*t;
            float bv0 = bfc[c], bv1 = bfc[c+1];
            *(float2*)(out + ra*EMBN + c) =
                make_float2(oacc[mi][nt][0] + bv0, oacc[mi][nt][1] + bv1);
            *(float2*)(out + (ra+8)*EMBN + c) =
                make_float2(oacc[mi][nt][2] + bv0, oacc[mi][nt][3] + bv1);
        }
    }
}

// ---------------------------------------------------------------------------
extern "C" void kernel_launch(void* const* d_in, const int* in_sizes, int n_in,
                              void* d_out, int out_size)
{
    const float* query = (const float*)d_in[0];
    const float* key_  = (const float*)d_in[1];
    const float* value = (const float*)d_in[2];
    const int*   mask  = (const int*)d_in[3];
    const float* Wq = (const float*)d_in[4];
    const float* bq = (const float*)d_in[5];
    const float* Wk = (const float*)d_in[6];
    const float* bk = (const float*)d_in[7];
    const float* Wv = (const float*)d_in[8];
    const float* bv = (const float*)d_in[9];
    const float* Wfc = (const float*)d_in[10];
    const float* bfc = (const float*)d_in[11];
    const float* relk = (const float*)d_in[12];
    const float* relv = (const float*)d_in[13];
    float* out = (float*)d_out;

    cudaFuncSetAttribute(attn_kernel, cudaFuncAttributeMaxDynamicSharedMemorySize, ATT_SMEM_BYTES);

    proj_kernel<<<dim3(1024, 3, 1), 256>>>(query, key_, value, Wq, bq, Wk, bk, Wv, bv);
    attn_kernel<<<dim3(16, 16, 4), 256, ATT_SMEM_BYTES>>>(mask, relk, relv);
    fc_kernel<<<dim3(32, 8, 1), 256>>>(Wfc, bfc, out);
}

// round 4
// speedup vs baseline: 3.5202x; 1.4057x over previous
#include <cuda_runtime.h>
#include <cuda_fp16.h>
#include <cstdint>
#include <cstddef>

#define BB   4
#define LL   1024
#define HH   16
#define DD   64
#define EMBN 1024
#define MAXREL 512
#define NREL (2*MAXREL + 1)

#define SH   72    // half stride, 64-wide tiles  (36 == 4 mod 32)
#define SH2  136   // half stride, 128-wide tiles (68 == 4 mod 32)
#define SF   132   // float stride for SrelF ring
#define SQ   68    // float stride for SQK

// Scratch (allocation-free rule: device globals)
__device__ __half g_qh [BB*LL*HH*DD];
__device__ __half g_kh [BB*LL*HH*DD];
__device__ __half g_vh [BB*LL*HH*DD];
__device__ __half g_ctx[BB*LL*HH*DD];
__device__ __half g_relk_h[NREL*DD];
__device__ __half g_relv_h[NREL*DD];
__device__ __half g_Wfc_h[EMBN*EMBN];
__device__ unsigned char g_mask8[BB*LL*LL];

// ---------------------------------------------------------------------------
#define MMA_F16(d0,d1,d2,d3,a0,a1,a2,a3,b0,b1)                               \
    asm volatile("mma.sync.aligned.m16n8k16.row.col.f32.f16.f16.f32 "        \
                 "{%0,%1,%2,%3}, {%4,%5,%6,%7}, {%8,%9}, {%0,%1,%2,%3};"     \
                 : "+f"(d0), "+f"(d1), "+f"(d2), "+f"(d3)                    \
                 : "r"(a0), "r"(a1), "r"(a2), "r"(a3), "r"(b0), "r"(b1))

__device__ __forceinline__ uint32_t ldh2(const __half* p) {
    return *(const uint32_t*)p;
}
__device__ __forceinline__ int clampdiff(int d) {
    return d < -MAXREL ? -MAXREL : (d > MAXREL ? MAXREL : d);
}

// ---------------------------------------------------------------------------
// Prep: fp16 conversions of constants + mask byte-pack. Grid-strided.
// ---------------------------------------------------------------------------
__global__ __launch_bounds__(256) void prep_kernel(
    const float* __restrict__ relk, const float* __restrict__ relv,
    const float* __restrict__ Wfc,  const int* __restrict__ mask)
{
    const int stride = blockDim.x * gridDim.x;
    for (int i = blockIdx.x*blockDim.x + threadIdx.x; i < NREL*DD; i += stride) {
        g_relk_h[i] = __float2half_rn(relk[i]);
        g_relv_h[i] = __float2half_rn(relv[i]);
    }
    for (int i = blockIdx.x*blockDim.x + threadIdx.x; i < EMBN*EMBN; i += stride)
        g_Wfc_h[i] = __float2half_rn(Wfc[i]);
    for (int i = blockIdx.x*blockDim.x + threadIdx.x; i < BB*LL*LL; i += stride)
        g_mask8[i] = (unsigned char)(mask[i] != 0);
}

// ---------------------------------------------------------------------------
// Projection (fma), outputs fp16: out[r,d] = X[r,:] . W[d,:] + b[d]
// ---------------------------------------------------------------------------
#define SA 68
__global__ __launch_bounds__(256) void proj_kernel(
    const float* __restrict__ query, const float* __restrict__ key_, const float* __restrict__ value,
    const float* __restrict__ Wq, const float* __restrict__ bq,
    const float* __restrict__ Wk, const float* __restrict__ bk,
    const float* __restrict__ Wv, const float* __restrict__ bv)
{
    __shared__ float Xs[64*SA];
    __shared__ float Ws[64*SA];
    __shared__ float bs[64];

    const float* X; const float* W; const float* bias; __half* out;
    if (blockIdx.y == 0)      { X = query; W = Wq; bias = bq; out = g_qh; }
    else if (blockIdx.y == 1) { X = key_;  W = Wk; bias = bk; out = g_kh; }
    else                      { X = value; W = Wv; bias = bv; out = g_vh; }

    const int tid = threadIdx.x;
    const size_t r0 = (size_t)blockIdx.x * 64;

    #pragma unroll
    for (int t = 0; t < 4; t++) {
        int idx = tid + t*256;
        int rr = idx >> 4, cc = (idx & 15) << 2;
        *(float4*)&Xs[rr*SA + cc] = *(const float4*)(X + (r0 + rr)*64 + cc);
        *(float4*)&Ws[rr*SA + cc] = *(const float4*)(W + (size_t)rr*64 + cc);
    }
    if (tid < 64) bs[tid] = bias[tid];
    __syncthreads();

    const int ty = tid >> 4, tx = tid & 15;
    float acc[4][4] = {};
    for (int e = 0; e < 64; e += 4) {
        float4 a[4], bb[4];
        #pragma unroll
        for (int ii = 0; ii < 4; ii++) a[ii]  = *(const float4*)&Xs[(ty + 16*ii)*SA + e];
        #pragma unroll
        for (int jj = 0; jj < 4; jj++) bb[jj] = *(const float4*)&Ws[(tx + 16*jj)*SA + e];
        #pragma unroll
        for (int ii = 0; ii < 4; ii++)
            #pragma unroll
            for (int jj = 0; jj < 4; jj++)
                acc[ii][jj] += a[ii].x*bb[jj].x + a[ii].y*bb[jj].y
                             + a[ii].z*bb[jj].z + a[ii].w*bb[jj].w;
    }
    #pragma unroll
    for (int ii = 0; ii < 4; ii++) {
        int i = ty + 16*ii;
        #pragma unroll
        for (int jj = 0; jj < 4; jj++) {
            int d = tx + 16*jj;
            out[(r0 + i)*64 + d] = __float2half_rn(acc[ii][jj] + bs[d]);
        }
    }
}

// ---------------------------------------------------------------------------
// Flash attention + relative bias, fp16 mma, register-prefetch pipeline.
// One block per (q-block 64, head, batch). 256 threads = 8 warps (4x2).
// ---------------------------------------------------------------------------
#define ATT_F_WORDS (64*SQ + 64*SF + 192)
#define ATT_H_WORDS (4*64*SH + 128*SH + 2*64*SH2)
#define ATT_SMEM_BYTES (ATT_F_WORDS*4 + ATT_H_WORDS*2)

__global__ __launch_bounds__(256) void attn_kernel()
{
    extern __shared__ float smf[];
    float*  SQK   = smf;                      // 64 x SQ
    float*  SrelF = SQK   + 64*SQ;            // 64 x SF  (128-col ring)
    float*  mrowS = SrelF + 64*SF;            // 64
    float*  lrowS = mrowS + 64;               // 64
    float*  cscS  = lrowS + 64;               // 64
    __half* Qh    = (__half*)(cscS + 64);     // 64 x SH
    __half* Kh    = Qh   + 64*SH;             // 64 x SH
    __half* Vt    = Kh   + 64*SH;             // 64 x SH   [d][kpos]
    __half* Ph    = Vt   + 64*SH;             // 64 x SH
    __half* Tkw   = Ph   + 64*SH;             // 128 x SH  rel_k ring [phys][e]
    __half* Tvwt  = Tkw  + 128*SH;            // 64 x SH2  rel_v ring [d][phys]
    __half* Bnd   = Tvwt + 64*SH2;            // 64 x SH2  band probs

    const int b  = blockIdx.z;
    const int h  = blockIdx.y;
    const int q0 = blockIdx.x * 64;
    const int tid  = threadIdx.x;
    const int warp = tid >> 5, lane = tid & 31;
    const int g = lane >> 2, t = lane & 3;
    const int wr = warp >> 1, wc = warp & 1;
    const int ty = tid >> 4, tx = tid & 15;
    const int r0 = wr*16 + g;

    // per-thread staging coordinates
    const int rrA = tid >> 3,        ccA = (tid & 7) << 3;        // chunk 0
    const int rrB = (tid+256) >> 3,  ccB = ((tid+256) & 7) << 3;  // chunk 1
    const int kp  = tid & 63, dg = tid >> 6;                      // V / relv transpose

    if (tid < 64) { mrowS[tid] = -1e30f; lrowS[tid] = 0.0f; }
    for (int i = tid; i < 64*SH2/2; i += 256) ((uint32_t*)Bnd)[i] = 0u;

    // stage Q (half, direct)
    {
        *(uint4*)&Qh[rrA*SH + ccA] = *(const uint4*)(g_qh + (((size_t)((b*LL + q0 + rrA)*HH + h)) << 6) + ccA);
        *(uint4*)&Qh[rrB*SH + ccB] = *(const uint4*)(g_qh + (((size_t)((b*LL + q0 + rrB)*HH + h)) << 6) + ccB);
    }

    // mask prefetch for tile 0
    uint32_t pM[4];
    #pragma unroll
    for (int ii = 0; ii < 4; ii++)
        pM[ii] = *(const uint32_t*)(g_mask8 + ((size_t)b*LL + q0 + ty + 16*ii)*LL + 0 + 4*tx);

    __syncthreads();

    // Q fragments in registers
    uint32_t qa[4][4];
    #pragma unroll
    for (int ks = 0; ks < 4; ks++) {
        qa[ks][0] = ldh2(&Qh[ r0    *SH + ks*16 + 2*t    ]);
        qa[ks][1] = ldh2(&Qh[(r0+8) *SH + ks*16 + 2*t    ]);
        qa[ks][2] = ldh2(&Qh[ r0    *SH + ks*16 + 2*t + 8]);
        qa[ks][3] = ldh2(&Qh[(r0+8) *SH + ks*16 + 2*t + 8]);
    }

    float oacc[4][4] = {};
    uint4 pK[2], pV[2], pRk[2], pRv[2];   // prefetch registers
    bool  havePf = false;

    for (int kt = 0; kt < 16; kt++) {
        const int k0 = kt * 64;
        const int d0 = k0 - q0;
        const int pb = ((kt + 1) & 1) << 6;   // phys base of NEW rel block
        const int kb = (kt & 1) << 6;         // ring rotation for lookups

        // ---- clear previous tile's band entries ----
        if (kt > 0) {
            const int kbp = ((kt - 1) & 1) << 6;
            const __half hz = __float2half_rn(0.0f);
            #pragma unroll
            for (int ii = 0; ii < 4; ii++) {
                int r = ty + 16*ii;
                #pragma unroll
                for (int cc = 0; cc < 4; cc++)
                    Bnd[r*SH2 + ((4*tx + cc - r + 63 + kbp) & 127)] = hz;
            }
        }

        // ---- staging ----
        if (!havePf) {
            // tile 0: direct staging (exposed once)
            *(uint4*)&Kh[rrA*SH + ccA] = *(const uint4*)(g_kh + (((size_t)((b*LL + k0 + rrA)*HH + h)) << 6) + ccA);
            *(uint4*)&Kh[rrB*SH + ccB] = *(const uint4*)(g_kh + (((size_t)((b*LL + k0 + rrB)*HH + h)) << 6) + ccB);
            {
                const __half* src = g_vh + (((size_t)((b*LL + k0 + kp)*HH + h)) << 6) + dg*16;
                uint4 v0 = *(const uint4*)(src), v1 = *(const uint4*)(src + 8);
                const __half* vh0 = (const __half*)&v0;
                const __half* vh1 = (const __half*)&v1;
                #pragma unroll
                for (int j = 0; j < 8; j++) {
                    Vt[(dg*16 + j    )*SH + kp] = vh0[j];
                    Vt[(dg*16 + j + 8)*SH + kp] = vh1[j];
                }
            }
            #pragma unroll
            for (int blk = 0; blk < 2; blk++) {
                const int pbX = blk << 6, jj0 = blk << 6;
                {
                    int dfA = clampdiff(d0 + jj0 + rrA - 63);
                    int dfB = clampdiff(d0 + jj0 + rrB - 63);
                    *(uint4*)&Tkw[(pbX + rrA)*SH + ccA] = *(const uint4*)(g_relk_h + ((size_t)(dfA + MAXREL) << 6) + ccA);
                    *(uint4*)&Tkw[(pbX + rrB)*SH + ccB] = *(const uint4*)(g_relk_h + ((size_t)(dfB + MAXREL) << 6) + ccB);
                }
                {
                    int df = clampdiff(d0 + jj0 + kp - 63);
                    const __half* src = g_relv_h + ((size_t)(df + MAXREL) << 6) + dg*16;
                    uint4 v0 = *(const uint4*)(src), v1 = *(const uint4*)(src + 8);
                    const __half* vh0 = (const __half*)&v0;
                    const __half* vh1 = (const __half*)&v1;
                    #pragma unroll
                    for (int j = 0; j < 8; j++) {
                        Tvwt[(dg*16 + j    )*SH2 + pbX + kp] = vh0[j];
                        Tvwt[(dg*16 + j + 8)*SH2 + pbX + kp] = vh1[j];
                    }
                }
            }
        } else {
            // STS from prefetch registers
            *(uint4*)&Kh[rrA*SH + ccA] = pK[0];
            *(uint4*)&Kh[rrB*SH + ccB] = pK[1];
            {
                const __half* vh0 = (const __half*)&pV[0];
                const __half* vh1 = (const __half*)&pV[1];
                #pragma unroll
                for (int j = 0; j < 8; j++) {
                    Vt[(dg*16 + j    )*SH + kp] = vh0[j];
                    Vt[(dg*16 + j + 8)*SH + kp] = vh1[j];
                }
            }
            *(uint4*)&Tkw[(pb + rrA)*SH + ccA] = pRk[0];
            *(uint4*)&Tkw[(pb + rrB)*SH + ccB] = pRk[1];
            {
                const __half* vh0 = (const __half*)&pRv[0];
                const __half* vh1 = (const __half*)&pRv[1];
                #pragma unroll
                for (int j = 0; j < 8; j++) {
                    Tvwt[(dg*16 + j    )*SH2 + pb + kp] = vh0[j];
                    Tvwt[(dg*16 + j + 8)*SH2 + pb + kp] = vh1[j];
                }
            }
        }
        __syncthreads();

        // ---- issue prefetch LDGs for tile kt+1 (latency hidden behind compute) ----
        if (kt < 15) {
            const int k0n = k0 + 64;
            const int d0n = k0n - q0;
            pK[0] = *(const uint4*)(g_kh + (((size_t)((b*LL + k0n + rrA)*HH + h)) << 6) + ccA);
            pK[1] = *(const uint4*)(g_kh + (((size_t)((b*LL + k0n + rrB)*HH + h)) << 6) + ccB);
            {
                const __half* src = g_vh + (((size_t)((b*LL + k0n + kp)*HH + h)) << 6) + dg*16;
                pV[0] = *(const uint4*)(src);
                pV[1] = *(const uint4*)(src + 8);
            }
            {
                int dfA = clampdiff(d0n + 64 + rrA - 63);
                int dfB = clampdiff(d0n + 64 + rrB - 63);
                pRk[0] = *(const uint4*)(g_relk_h + ((size_t)(dfA + MAXREL) << 6) + ccA);
                pRk[1] = *(const uint4*)(g_relk_h + ((size_t)(dfB + MAXREL) << 6) + ccB);
            }
            {
                int df = clampdiff(d0n + 64 + kp - 63);
                const __half* src = g_relv_h + ((size_t)(df + MAXREL) << 6) + dg*16;
                pRv[0] = *(const uint4*)(src);
                pRv[1] = *(const uint4*)(src + 8);
            }
            havePf = true;
        }

        // ---- GEMM1a: QK scores ----
        #pragma unroll
        for (int nt = 0; nt < 4; nt++) {
            const int n0 = wc*32 + nt*8;
            const __half* Bb = Kh + (n0 + g)*SH;
            float c0 = 0.f, c1 = 0.f, c2 = 0.f, c3 = 0.f;
            #pragma unroll
            for (int ks = 0; ks < 4; ks++) {
                uint32_t b0 = ldh2(Bb + ks*16 + 2*t);
                uint32_t b1 = ldh2(Bb + ks*16 + 2*t + 8);
                MMA_F16(c0, c1, c2, c3, qa[ks][0], qa[ks][1], qa[ks][2], qa[ks][3], b0, b1);
            }
            *(float2*)&SQK[ r0   *SQ + n0 + 2*t] = make_float2(c0, c1);
            *(float2*)&SQK[(r0+8)*SQ + n0 + 2*t] = make_float2(c2, c3);
        }
        // ---- GEMM1b: rel scores for NEW block(s) ----
        const int nblk = (kt == 0) ? 2 : 1;
        for (int blk = 0; blk < nblk; blk++) {
            const int pbX = (kt == 0) ? (blk << 6) : pb;
            #pragma unroll
            for (int nt = 0; nt < 4; nt++) {
                const int nn = wc*32 + nt*8;
                const __half* Bb = Tkw + (pbX + nn + g)*SH;
                float c0 = 0.f, c1 = 0.f, c2 = 0.f, c3 = 0.f;
                #pragma unroll
                for (int ks = 0; ks < 4; ks++) {
                    uint32_t b0 = ldh2(Bb + ks*16 + 2*t);
                    uint32_t b1 = ldh2(Bb + ks*16 + 2*t + 8);
                    MMA_F16(c0, c1, c2, c3, qa[ks][0], qa[ks][1], qa[ks][2], qa[ks][3], b0, b1);
                }
                *(float2*)&SrelF[ r0   *SF + pbX + nn + 2*t] = make_float2(c0, c1);
                *(float2*)&SrelF[(r0+8)*SF + pbX + nn + 2*t] = make_float2(c2, c3);
            }
        }
        __syncthreads();

        // ---- softmax ----
        #pragma unroll
        for (int ii = 0; ii < 4; ii++) {
            const int r = ty + 16*ii;
            float4 s4 = *(const float4*)&SQK[r*SQ + 4*tx];
            const uint32_t m = pM[ii];
            float sv[4];
            sv[0] = (m & 0x000000ffu) ? s4.x : -1e20f;
            sv[1] = (m & 0x0000ff00u) ? s4.y : -1e20f;
            sv[2] = (m & 0x00ff0000u) ? s4.z : -1e20f;
            sv[3] = (m & 0xff000000u) ? s4.w : -1e20f;
            #pragma unroll
            for (int cc = 0; cc < 4; cc++) {
                int c = 4*tx + cc;
                sv[cc] = (sv[cc] + SrelF[r*SF + ((c - r + 63 + kb) & 127)]) * 0.125f;
            }
            float rm = fmaxf(fmaxf(sv[0], sv[1]), fmaxf(sv[2], sv[3]));
            #pragma unroll
            for (int o = 1; o < 16; o <<= 1)
                rm = fmaxf(rm, __shfl_xor_sync(0xffffffffu, rm, o));
            float mold = mrowS[r];
            float mn = fmaxf(mold, rm);
            float csc = __expf(mold - mn);
            float p[4], ls = 0.f;
            #pragma unroll
            for (int cc = 0; cc < 4; cc++) { p[cc] = __expf(sv[cc] - mn); ls += p[cc]; }
            #pragma unroll
            for (int o = 1; o < 16; o <<= 1)
                ls += __shfl_xor_sync(0xffffffffu, ls, o);
            if (tx == 0) {
                mrowS[r] = mn;
                cscS[r]  = csc;
                lrowS[r] = lrowS[r]*csc + ls;
            }
            uint2 ph;
            {
                __half2 h0 = __floats2half2_rn(p[0], p[1]);
                __half2 h1 = __floats2half2_rn(p[2], p[3]);
                ph.x = *(uint32_t*)&h0; ph.y = *(uint32_t*)&h1;
            }
            *(uint2*)&Ph[r*SH + 4*tx] = ph;
            #pragma unroll
            for (int cc = 0; cc < 4; cc++) {
                int c = 4*tx + cc;
                Bnd[r*SH2 + ((c - r + 63 + kb) & 127)] = __float2half_rn(p[cc]);
            }
        }
        // mask prefetch for next tile (consumed next softmax; hidden behind GEMM2+staging+GEMM1)
        if (kt < 15) {
            #pragma unroll
            for (int ii = 0; ii < 4; ii++)
                pM[ii] = *(const uint32_t*)(g_mask8 + ((size_t)b*LL + q0 + ty + 16*ii)*LL + (k0 + 64) + 4*tx);
        }
        __syncthreads();

        // ---- GEMM2: oacc = csc*oacc + P@V + Pband@Tvw ----
        {
            const float f0 = cscS[r0], f1 = cscS[r0+8];
            #pragma unroll
            for (int nt = 0; nt < 4; nt++) {
                oacc[nt][0] *= f0; oacc[nt][1] *= f0;
                oacc[nt][2] *= f1; oacc[nt][3] *= f1;
            }
            #pragma unroll
            for (int ks = 0; ks < 4; ks++) {
                uint32_t a0 = ldh2(&Ph[ r0   *SH + ks*16 + 2*t    ]);
                uint32_t a1 = ldh2(&Ph[(r0+8)*SH + ks*16 + 2*t    ]);
                uint32_t a2 = ldh2(&Ph[ r0   *SH + ks*16 + 2*t + 8]);
                uint32_t a3 = ldh2(&Ph[(r0+8)*SH + ks*16 + 2*t + 8]);
                #pragma unroll
                for (int nt = 0; nt < 4; nt++) {
                    const __half* Bb = Vt + (wc*32 + nt*8 + g)*SH;
                    uint32_t b0 = ldh2(Bb + ks*16 + 2*t);
                    uint32_t b1 = ldh2(Bb + ks*16 + 2*t + 8);
                    MMA_F16(oacc[nt][0], oacc[nt][1], oacc[nt][2], oacc[nt][3],
                            a0, a1, a2, a3, b0, b1);
                }
            }
            #pragma unroll
            for (int ks = 0; ks < 8; ks++) {
                uint32_t a0 = ldh2(&Bnd[ r0   *SH2 + ks*16 + 2*t    ]);
                uint32_t a1 = ldh2(&Bnd[(r0+8)*SH2 + ks*16 + 2*t    ]);
                uint32_t a2 = ldh2(&Bnd[ r0   *SH2 + ks*16 + 2*t + 8]);
                uint32_t a3 = ldh2(&Bnd[(r0+8)*SH2 + ks*16 + 2*t + 8]);
                #pragma unroll
                for (int nt = 0; nt < 4; nt++) {
                    const __half* Bb = Tvwt + (wc*32 + nt*8 + g)*SH2;
                    uint32_t b0 = ldh2(Bb + ks*16 + 2*t);
                    uint32_t b1 = ldh2(Bb + ks*16 + 2*t + 8);
                    MMA_F16(oacc[nt][0], oacc[nt][1], oacc[nt][2], oacc[nt][3],
                            a0, a1, a2, a3, b0, b1);
                }
            }
        }
        __syncthreads();
    }

    // ---- epilogue ----
    {
        const float l0 = 1.0f / lrowS[r0];
        const float l1 = 1.0f / lrowS[r0 + 8];
        const size_t base0 = (((size_t)((b*LL + q0 + r0    )*HH + h)) << 6);
        const size_t base1 = (((size_t)((b*LL + q0 + r0 + 8)*HH + h)) << 6);
        #pragma unroll
        for (int nt = 0; nt < 4; nt++) {
            int c = wc*32 + nt*8 + 2*t;
            __half2 h0 = __floats2half2_rn(oacc[nt][0]*l0, oacc[nt][1]*l0);
            __half2 h1 = __floats2half2_rn(oacc[nt][2]*l1, oacc[nt][3]*l1);
            *(uint32_t*)(g_ctx + base0 + c) = *(uint32_t*)&h0;
            *(uint32_t*)(g_ctx + base1 + c) = *(uint32_t*)&h1;
        }
    }
}

// ---------------------------------------------------------------------------
// Final FC, fp16 mma, 128x128 tiles, half inputs. grid (32, 8), 256 threads.
// ---------------------------------------------------------------------------
__global__ __launch_bounds__(256) void fc_kernel(
    const float* __restrict__ bfc, float* __restrict__ out)
{
    __shared__ __half Xs[128*SH];
    __shared__ __half Ws[128*SH];

    const int tid  = threadIdx.x;
    const int warp = tid >> 5, lane = tid & 31;
    const int g = lane >> 2, t = lane & 3;
    const int wr = warp >> 1, wc = warp & 1;
    const size_t r0 = (size_t)blockIdx.x * 128;
    const size_t n0 = (size_t)blockIdx.y * 128;

    float oacc[2][8][4] = {};

    for (int e0 = 0; e0 < EMBN; e0 += 64) {
        #pragma unroll
        for (int tt = 0; tt < 4; tt++) {
            int idx = tid + tt*256;
            int rr = idx >> 3, cc = (idx & 7) << 3;
            *(uint4*)&Xs[rr*SH + cc] = *(const uint4*)(g_ctx   + (r0 + rr)*EMBN + e0 + cc);
            *(uint4*)&Ws[rr*SH + cc] = *(const uint4*)(g_Wfc_h + (n0 + rr)*EMBN + e0 + cc);
        }
        __syncthreads();
        #pragma unroll
        for (int ks = 0; ks < 4; ks++) {
            uint32_t a[2][4];
            #pragma unroll
            for (int mi = 0; mi < 2; mi++) {
                int ar = wr*32 + mi*16 + g;
                a[mi][0] = ldh2(&Xs[ ar   *SH + ks*16 + 2*t    ]);
                a[mi][1] = ldh2(&Xs[(ar+8)*SH + ks*16 + 2*t    ]);
                a[mi][2] = ldh2(&Xs[ ar   *SH + ks*16 + 2*t + 8]);
                a[mi][3] = ldh2(&Xs[(ar+8)*SH + ks*16 + 2*t + 8]);
            }
            #pragma unroll
            for (int nt = 0; nt < 8; nt++) {
                const __half* Bb = Ws + (wc*64 + nt*8 + g)*SH;
                uint32_t b0 = ldh2(Bb + ks*16 + 2*t);
                uint32_t b1 = ldh2(Bb + ks*16 + 2*t + 8);
                #pragma unroll
                for (int mi = 0; mi < 2; mi++)
                    MMA_F16(oacc[mi][nt][0], oacc[mi][nt][1], oacc[mi][nt][2], oacc[mi][nt][3],
                            a[mi][0], a[mi][1], a[mi][2], a[mi][3], b0, b1);
            }
        }
        __syncthreads();
    }

    #pragma unroll
    for (int mi = 0; mi < 2; mi++) {
        size_t ra = r0 + wr*32 + mi*16 + g;
        #pragma unroll
        for (int nt = 0; nt < 8; nt++) {
            size_t c = n0 + wc*64 + nt*8 + 2*t;
            float bv0 = bfc[c], bv1 = bfc[c+1];
            *(float2*)(out + ra*EMBN + c) =
                make_float2(oacc[mi][nt][0] + bv0, oacc[mi][nt][1] + bv1);
            *(float2*)(out + (ra+8)*EMBN + c) =
                make_float2(oacc[mi][nt][2] + bv0, oacc[mi][nt][3] + bv1);
        }
    }
}

// ---------------------------------------------------------------------------
extern "C" void kernel_launch(void* const* d_in, const int* in_sizes, int n_in,
                              void* d_out, int out_size)
{
    const float* query = (const float*)d_in[0];
    const float* key_  = (const float*)d_in[1];
    const float* value = (const float*)d_in[2];
    const int*   mask  = (const int*)d_in[3];
    const float* Wq = (const float*)d_in[4];
    const float* bq = (const float*)d_in[5];
    const float* Wk = (const float*)d_in[6];
    const float* bk = (const float*)d_in[7];
    const float* Wv = (const float*)d_in[8];
    const float* bv = (const float*)d_in[9];
    const float* Wfc = (const float*)d_in[10];
    const float* bfc = (const float*)d_in[11];
    const float* relk = (const float*)d_in[12];
    const float* relv = (const float*)d_in[13];
    float* out = (float*)d_out;

    cudaFuncSetAttribute(attn_kernel, cudaFuncAttributeMaxDynamicSharedMemorySize, ATT_SMEM_BYTES);

    prep_kernel<<<1024, 256>>>(relk, relv, Wfc, mask);
    proj_kernel<<<dim3(1024, 3, 1), 256>>>(query, key_, value, Wq, bq, Wk, bk, Wv, bv);
    attn_kernel<<<dim3(16, 16, 4), 256, ATT_SMEM_BYTES>>>();
    fc_kernel<<<dim3(32, 8, 1), 256>>>(bfc, out);
}

// round 5
// speedup vs baseline: 3.8347x; 1.0893x over previous
#include <cuda_runtime.h>
#include <cuda_fp16.h>
#include <cstdint>
#include <cstddef>

#define BB   4
#define LL   1024
#define HH   16
#define DD   64
#define EMBN 1024
#define MAXREL 512
#define NREL (2*MAXREL + 1)

#define SH   72    // half stride, 64-wide tiles  (36 == 4 mod 32)
#define SH2  136   // half stride, 128-wide tiles (68 == 4 mod 32)
#define SF   132   // float stride for SrelF ring
#define SQ   68    // float stride for SQK

// Scratch (allocation-free rule: device globals)
__device__ __half g_qh [BB*LL*HH*DD];
__device__ __half g_kh [BB*LL*HH*DD];
__device__ __half g_vh [BB*LL*HH*DD];
__device__ __half g_ctx[BB*LL*HH*DD];
__device__ __half g_relk_h[NREL*DD];
__device__ __half g_relv_h[NREL*DD];
__device__ __half g_Wfc_h[EMBN*EMBN];
__device__ unsigned char g_mask8[BB*LL*LL];

// ---------------------------------------------------------------------------
#define MMA_F16(d0,d1,d2,d3,a0,a1,a2,a3,b0,b1)                               \
    asm volatile("mma.sync.aligned.m16n8k16.row.col.f32.f16.f16.f32 "        \
                 "{%0,%1,%2,%3}, {%4,%5,%6,%7}, {%8,%9}, {%0,%1,%2,%3};"     \
                 : "+f"(d0), "+f"(d1), "+f"(d2), "+f"(d3)                    \
                 : "r"(a0), "r"(a1), "r"(a2), "r"(a3), "r"(b0), "r"(b1))

__device__ __forceinline__ uint32_t ldh2(const __half* p) {
    return *(const uint32_t*)p;
}
__device__ __forceinline__ int clampdiff(int d) {
    return d < -MAXREL ? -MAXREL : (d > MAXREL ? MAXREL : d);
}

// ---------------------------------------------------------------------------
// Prep: fp16 conversions of constants + mask byte-pack. Grid-strided.
// ---------------------------------------------------------------------------
__global__ __launch_bounds__(256) void prep_kernel(
    const float* __restrict__ relk, const float* __restrict__ relv,
    const float* __restrict__ Wfc,  const int* __restrict__ mask)
{
    const int stride = blockDim.x * gridDim.x;
    for (int i = blockIdx.x*blockDim.x + threadIdx.x; i < NREL*DD; i += stride) {
        g_relk_h[i] = __float2half_rn(relk[i]);
        g_relv_h[i] = __float2half_rn(relv[i]);
    }
    for (int i = blockIdx.x*blockDim.x + threadIdx.x; i < EMBN*EMBN; i += stride)
        g_Wfc_h[i] = __float2half_rn(Wfc[i]);
    for (int i = blockIdx.x*blockDim.x + threadIdx.x; i < BB*LL*LL; i += stride)
        g_mask8[i] = (unsigned char)(mask[i] != 0);
}

// ---------------------------------------------------------------------------
// Projection (fma), outputs fp16: out[r,d] = X[r,:] . W[d,:] + b[d]
// ---------------------------------------------------------------------------
#define SA 68
__global__ __launch_bounds__(256) void proj_kernel(
    const float* __restrict__ query, const float* __restrict__ key_, const float* __restrict__ value,
    const float* __restrict__ Wq, const float* __restrict__ bq,
    const float* __restrict__ Wk, const float* __restrict__ bk,
    const float* __restrict__ Wv, const float* __restrict__ bv)
{
    __shared__ float Xs[64*SA];
    __shared__ float Ws[64*SA];
    __shared__ float bs[64];

    const float* X; const float* W; const float* bias; __half* out;
    if (blockIdx.y == 0)      { X = query; W = Wq; bias = bq; out = g_qh; }
    else if (blockIdx.y == 1) { X = key_;  W = Wk; bias = bk; out = g_kh; }
    else                      { X = value; W = Wv; bias = bv; out = g_vh; }

    const int tid = threadIdx.x;
    const size_t r0 = (size_t)blockIdx.x * 64;

    #pragma unroll
    for (int t = 0; t < 4; t++) {
        int idx = tid + t*256;
        int rr = idx >> 4, cc = (idx & 15) << 2;
        *(float4*)&Xs[rr*SA + cc] = *(const float4*)(X + (r0 + rr)*64 + cc);
        *(float4*)&Ws[rr*SA + cc] = *(const float4*)(W + (size_t)rr*64 + cc);
    }
    if (tid < 64) bs[tid] = bias[tid];
    __syncthreads();

    const int ty = tid >> 4, tx = tid & 15;
    float acc[4][4] = {};
    for (int e = 0; e < 64; e += 4) {
        float4 a[4], bb[4];
        #pragma unroll
        for (int ii = 0; ii < 4; ii++) a[ii]  = *(const float4*)&Xs[(ty + 16*ii)*SA + e];
        #pragma unroll
        for (int jj = 0; jj < 4; jj++) bb[jj] = *(const float4*)&Ws[(tx + 16*jj)*SA + e];
        #pragma unroll
        for (int ii = 0; ii < 4; ii++)
            #pragma unroll
            for (int jj = 0; jj < 4; jj++)
                acc[ii][jj] += a[ii].x*bb[jj].x + a[ii].y*bb[jj].y
                             + a[ii].z*bb[jj].z + a[ii].w*bb[jj].w;
    }
    #pragma unroll
    for (int ii = 0; ii < 4; ii++) {
        int i = ty + 16*ii;
        #pragma unroll
        for (int jj = 0; jj < 4; jj++) {
            int d = tx + 16*jj;
            out[(r0 + i)*64 + d] = __float2half_rn(acc[ii][jj] + bs[d]);
        }
    }
}

// ---------------------------------------------------------------------------
// Flash attention + relative bias, fp16 mma, register-prefetch pipeline.
// One block per (q-block 64, head, batch). 512 threads = 16 warps (4x4).
// ---------------------------------------------------------------------------
#define ATT_F_WORDS (64*SQ + 64*SF + 192)
#define ATT_H_WORDS (4*64*SH + 128*SH + 2*64*SH2)
#define ATT_SMEM_BYTES (ATT_F_WORDS*4 + ATT_H_WORDS*2)

__global__ __launch_bounds__(512) void attn_kernel()
{
    extern __shared__ float smf[];
    float*  SQK   = smf;                      // 64 x SQ
    float*  SrelF = SQK   + 64*SQ;            // 64 x SF  (128-col ring)
    float*  mrowS = SrelF + 64*SF;            // 64
    float*  lrowS = mrowS + 64;               // 64
    float*  cscS  = lrowS + 64;               // 64
    __half* Qh    = (__half*)(cscS + 64);     // 64 x SH
    __half* Kh    = Qh   + 64*SH;             // 64 x SH
    __half* Vt    = Kh   + 64*SH;             // 64 x SH   [d][kpos]
    __half* Ph    = Vt   + 64*SH;             // 64 x SH
    __half* Tkw   = Ph   + 64*SH;             // 128 x SH  rel_k ring [phys][e]
    __half* Tvwt  = Tkw  + 128*SH;            // 64 x SH2  rel_v ring [d][phys]
    __half* Bnd   = Tvwt + 64*SH2;            // 64 x SH2  band probs

    const int b  = blockIdx.z;
    const int h  = blockIdx.y;
    const int q0 = blockIdx.x * 64;
    const int tid  = threadIdx.x;
    const int warp = tid >> 5, lane = tid & 31;
    const int g = lane >> 2, t = lane & 3;
    const int wr = warp >> 2, wc = warp & 3;     // 4x4 warp grid
    const int r0 = wr*16 + g;

    // softmax coords: 8 threads per row, 8 cols each
    const int srow = tid >> 3;
    const int scol = (tid & 7) << 3;

    // staging coords: one uint4 (8 halves) per thread over a 64x64 tile
    const int rr = tid >> 3, cc = (tid & 7) << 3;
    const int kp = tid & 63, dg = tid >> 6;      // transpose: 8 d's per thread

    if (tid < 64) { mrowS[tid] = -1e30f; lrowS[tid] = 0.0f; }
    for (int i = tid; i < 64*SH2/2; i += 512) ((uint32_t*)Bnd)[i] = 0u;

    // stage Q
    *(uint4*)&Qh[rr*SH + cc] =
        *(const uint4*)(g_qh + (((size_t)((b*LL + q0 + rr)*HH + h)) << 6) + cc);

    // mask prefetch for tile 0 (8 bytes per thread)
    uint2 pM = *(const uint2*)(g_mask8 + ((size_t)b*LL + q0 + srow)*LL + scol);

    __syncthreads();

    // Q fragments in registers
    uint32_t qa[4][4];
    #pragma unroll
    for (int ks = 0; ks < 4; ks++) {
        qa[ks][0] = ldh2(&Qh[ r0    *SH + ks*16 + 2*t    ]);
        qa[ks][1] = ldh2(&Qh[(r0+8) *SH + ks*16 + 2*t    ]);
        qa[ks][2] = ldh2(&Qh[ r0    *SH + ks*16 + 2*t + 8]);
        qa[ks][3] = ldh2(&Qh[(r0+8) *SH + ks*16 + 2*t + 8]);
    }

    float oacc[2][4] = {};
    uint4 pK, pV, pRk, pRv;
    bool  havePf = false;

    for (int kt = 0; kt < 16; kt++) {
        const int k0 = kt * 64;
        const int d0 = k0 - q0;
        const int pb = ((kt + 1) & 1) << 6;
        const int kb = (kt & 1) << 6;

        // ---- clear previous tile's band entries (row srow, 8 cols) ----
        if (kt > 0) {
            const int kbp = ((kt - 1) & 1) << 6;
            const __half hz = __float2half_rn(0.0f);
            #pragma unroll
            for (int ccx = 0; ccx < 8; ccx++)
                Bnd[srow*SH2 + ((scol + ccx - srow + 63 + kbp) & 127)] = hz;
        }

        // ---- staging ----
        if (!havePf) {
            *(uint4*)&Kh[rr*SH + cc] =
                *(const uint4*)(g_kh + (((size_t)((b*LL + k0 + rr)*HH + h)) << 6) + cc);
            {
                const __half* src = g_vh + (((size_t)((b*LL + k0 + kp)*HH + h)) << 6) + dg*8;
                uint4 v0 = *(const uint4*)src;
                const __half* vh = (const __half*)&v0;
                #pragma unroll
                for (int j = 0; j < 8; j++) Vt[(dg*8 + j)*SH + kp] = vh[j];
            }
            #pragma unroll
            for (int blk = 0; blk < 2; blk++) {
                const int pbX = blk << 6, jj0 = blk << 6;
                {
                    int df = clampdiff(d0 + jj0 + rr - 63);
                    *(uint4*)&Tkw[(pbX + rr)*SH + cc] =
                        *(const uint4*)(g_relk_h + ((size_t)(df + MAXREL) << 6) + cc);
                }
                {
                    int df = clampdiff(d0 + jj0 + kp - 63);
                    const __half* src = g_relv_h + ((size_t)(df + MAXREL) << 6) + dg*8;
                    uint4 v0 = *(const uint4*)src;
                    const __half* vh = (const __half*)&v0;
                    #pragma unroll
                    for (int j = 0; j < 8; j++) Tvwt[(dg*8 + j)*SH2 + pbX + kp] = vh[j];
                }
            }
        } else {
            *(uint4*)&Kh[rr*SH + cc] = pK;
            {
                const __half* vh = (const __half*)&pV;
                #pragma unroll
                for (int j = 0; j < 8; j++) Vt[(dg*8 + j)*SH + kp] = vh[j];
            }
            *(uint4*)&Tkw[(pb + rr)*SH + cc] = pRk;
            {
                const __half* vh = (const __half*)&pRv;
                #pragma unroll
                for (int j = 0; j < 8; j++) Tvwt[(dg*8 + j)*SH2 + pb + kp] = vh[j];
            }
        }
        __syncthreads();

        // ---- issue prefetch LDGs for tile kt+1 ----
        if (kt < 15) {
            const int k0n = k0 + 64;
            const int d0n = k0n - q0;
            pK = *(const uint4*)(g_kh + (((size_t)((b*LL + k0n + rr)*HH + h)) << 6) + cc);
            pV = *(const uint4*)(g_vh + (((size_t)((b*LL + k0n + kp)*HH + h)) << 6) + dg*8);
            {
                int df = clampdiff(d0n + 64 + rr - 63);
                pRk = *(const uint4*)(g_relk_h + ((size_t)(df + MAXREL) << 6) + cc);
            }
            {
                int df = clampdiff(d0n + 64 + kp - 63);
                pRv = *(const uint4*)(g_relv_h + ((size_t)(df + MAXREL) << 6) + dg*8);
            }
            havePf = true;
        }

        // ---- GEMM1a: QK scores (each warp: n = wc*16 .. +15) ----
        #pragma unroll
        for (int nt = 0; nt < 2; nt++) {
            const int n0 = wc*16 + nt*8;
            const __half* Bb = Kh + (n0 + g)*SH;
            float c0 = 0.f, c1 = 0.f, c2 = 0.f, c3 = 0.f;
            #pragma unroll
            for (int ks = 0; ks < 4; ks++) {
                uint32_t b0 = ldh2(Bb + ks*16 + 2*t);
                uint32_t b1 = ldh2(Bb + ks*16 + 2*t + 8);
                MMA_F16(c0, c1, c2, c3, qa[ks][0], qa[ks][1], qa[ks][2], qa[ks][3], b0, b1);
            }
            *(float2*)&SQK[ r0   *SQ + n0 + 2*t] = make_float2(c0, c1);
            *(float2*)&SQK[(r0+8)*SQ + n0 + 2*t] = make_float2(c2, c3);
        }
        // ---- GEMM1b: rel scores for NEW block(s) ----
        const int nblk = (kt == 0) ? 2 : 1;
        for (int blk = 0; blk < nblk; blk++) {
            const int pbX = (kt == 0) ? (blk << 6) : pb;
            #pragma unroll
            for (int nt = 0; nt < 2; nt++) {
                const int nn = wc*16 + nt*8;
                const __half* Bb = Tkw + (pbX + nn + g)*SH;
                float c0 = 0.f, c1 = 0.f, c2 = 0.f, c3 = 0.f;
                #pragma unroll
                for (int ks = 0; ks < 4; ks++) {
                    uint32_t b0 = ldh2(Bb + ks*16 + 2*t);
                    uint32_t b1 = ldh2(Bb + ks*16 + 2*t + 8);
                    MMA_F16(c0, c1, c2, c3, qa[ks][0], qa[ks][1], qa[ks][2], qa[ks][3], b0, b1);
                }
                *(float2*)&SrelF[ r0   *SF + pbX + nn + 2*t] = make_float2(c0, c1);
                *(float2*)&SrelF[(r0+8)*SF + pbX + nn + 2*t] = make_float2(c2, c3);
            }
        }
        __syncthreads();

        // ---- softmax: one row per 8 threads, 8 cols per thread ----
        {
            float4 s4a = *(const float4*)&SQK[srow*SQ + scol];
            float4 s4b = *(const float4*)&SQK[srow*SQ + scol + 4];
            float sv[8];
            sv[0] = (pM.x & 0x000000ffu) ? s4a.x : -1e20f;
            sv[1] = (pM.x & 0x0000ff00u) ? s4a.y : -1e20f;
            sv[2] = (pM.x & 0x00ff0000u) ? s4a.z : -1e20f;
            sv[3] = (pM.x & 0xff000000u) ? s4a.w : -1e20f;
            sv[4] = (pM.y & 0x000000ffu) ? s4b.x : -1e20f;
            sv[5] = (pM.y & 0x0000ff00u) ? s4b.y : -1e20f;
            sv[6] = (pM.y & 0x00ff0000u) ? s4b.z : -1e20f;
            sv[7] = (pM.y & 0xff000000u) ? s4b.w : -1e20f;
            #pragma unroll
            for (int ccx = 0; ccx < 8; ccx++) {
                int c = scol + ccx;
                sv[ccx] = (sv[ccx] + SrelF[srow*SF + ((c - srow + 63 + kb) & 127)]) * 0.125f;
            }
            float rm = sv[0];
            #pragma unroll
            for (int ccx = 1; ccx < 8; ccx++) rm = fmaxf(rm, sv[ccx]);
            #pragma unroll
            for (int o = 1; o < 8; o <<= 1)
                rm = fmaxf(rm, __shfl_xor_sync(0xffffffffu, rm, o));
            float mold = mrowS[srow];
            float mn = fmaxf(mold, rm);
            float csc = __expf(mold - mn);
            float p[8], ls = 0.f;
            #pragma unroll
            for (int ccx = 0; ccx < 8; ccx++) { p[ccx] = __expf(sv[ccx] - mn); ls += p[ccx]; }
            #pragma unroll
            for (int o = 1; o < 8; o <<= 1)
                ls += __shfl_xor_sync(0xffffffffu, ls, o);
            if ((tid & 7) == 0) {
                mrowS[srow] = mn;
                cscS[srow]  = csc;
                lrowS[srow] = lrowS[srow]*csc + ls;
            }
            // probs -> Ph (half, uint4 = 8 halves) + band scatter
            uint4 ph;
            {
                __half2 h0 = __floats2half2_rn(p[0], p[1]);
                __half2 h1 = __floats2half2_rn(p[2], p[3]);
                __half2 h2 = __floats2half2_rn(p[4], p[5]);
                __half2 h3 = __floats2half2_rn(p[6], p[7]);
                ph.x = *(uint32_t*)&h0; ph.y = *(uint32_t*)&h1;
                ph.z = *(uint32_t*)&h2; ph.w = *(uint32_t*)&h3;
            }
            *(uint4*)&Ph[srow*SH + scol] = ph;
            #pragma unroll
            for (int ccx = 0; ccx < 8; ccx++) {
                int c = scol + ccx;
                Bnd[srow*SH2 + ((c - srow + 63 + kb) & 127)] = __float2half_rn(p[ccx]);
            }
        }
        // mask prefetch for next tile
        if (kt < 15)
            pM = *(const uint2*)(g_mask8 + ((size_t)b*LL + q0 + srow)*LL + (k0 + 64) + scol);
        __syncthreads();

        // ---- GEMM2: oacc = csc*oacc + P@V + Pband@Tvw (n = wc*16..+15) ----
        {
            const float f0 = cscS[r0], f1 = cscS[r0+8];
            #pragma unroll
            for (int nt = 0; nt < 2; nt++) {
                oacc[nt][0] *= f0; oacc[nt][1] *= f0;
                oacc[nt][2] *= f1; oacc[nt][3] *= f1;
            }
            #pragma unroll
            for (int ks = 0; ks < 4; ks++) {
                uint32_t a0 = ldh2(&Ph[ r0   *SH + ks*16 + 2*t    ]);
                uint32_t a1 = ldh2(&Ph[(r0+8)*SH + ks*16 + 2*t    ]);
                uint32_t a2 = ldh2(&Ph[ r0   *SH + ks*16 + 2*t + 8]);
                uint32_t a3 = ldh2(&Ph[(r0+8)*SH + ks*16 + 2*t + 8]);
                #pragma unroll
                for (int nt = 0; nt < 2; nt++) {
                    const __half* Bb = Vt + (wc*16 + nt*8 + g)*SH;
                    uint32_t b0 = ldh2(Bb + ks*16 + 2*t);
                    uint32_t b1 = ldh2(Bb + ks*16 + 2*t + 8);
                    MMA_F16(oacc[nt][0], oacc[nt][1], oacc[nt][2], oacc[nt][3],
                            a0, a1, a2, a3, b0, b1);
                }
            }
            #pragma unroll
            for (int ks = 0; ks < 8; ks++) {
                uint32_t a0 = ldh2(&Bnd[ r0   *SH2 + ks*16 + 2*t    ]);
                uint32_t a1 = ldh2(&Bnd[(r0+8)*SH2 + ks*16 + 2*t    ]);
                uint32_t a2 = ldh2(&Bnd[ r0   *SH2 + ks*16 + 2*t + 8]);
                uint32_t a3 = ldh2(&Bnd[(r0+8)*SH2 + ks*16 + 2*t + 8]);
                #pragma unroll
                for (int nt = 0; nt < 2; nt++) {
                    const __half* Bb = Tvwt + (wc*16 + nt*8 + g)*SH2;
                    uint32_t b0 = ldh2(Bb + ks*16 + 2*t);
                    uint32_t b1 = ldh2(Bb + ks*16 + 2*t + 8);
                    MMA_F16(oacc[nt][0], oacc[nt][1], oacc[nt][2], oacc[nt][3],
                            a0, a1, a2, a3, b0, b1);
                }
            }
        }
        __syncthreads();
    }

    // ---- epilogue ----
    {
        const float l0 = 1.0f / lrowS[r0];
        const float l1 = 1.0f / lrowS[r0 + 8];
        const size_t base0 = (((size_t)((b*LL + q0 + r0    )*HH + h)) << 6);
        const size_t base1 = (((size_t)((b*LL + q0 + r0 + 8)*HH + h)) << 6);
        #pragma unroll
        for (int nt = 0; nt < 2; nt++) {
            int c = wc*16 + nt*8 + 2*t;
            __half2 h0 = __floats2half2_rn(oacc[nt][0]*l0, oacc[nt][1]*l0);
            __half2 h1 = __floats2half2_rn(oacc[nt][2]*l1, oacc[nt][3]*l1);
            *(uint32_t*)(g_ctx + base0 + c) = *(uint32_t*)&h0;
            *(uint32_t*)(g_ctx + base1 + c) = *(uint32_t*)&h1;
        }
    }
}

// ---------------------------------------------------------------------------
// Final FC, fp16 mma, 128x128 tiles, 512 threads (4x4 warps), reg prefetch.
// ---------------------------------------------------------------------------
__global__ __launch_bounds__(512) void fc_kernel(
    const float* __restrict__ bfc, float* __restrict__ out)
{
    __shared__ __half Xs[128*SH];
    __shared__ __half Ws[128*SH];

    const int tid  = threadIdx.x;
    const int warp = tid >> 5, lane = tid & 31;
    const int g = lane >> 2, t = lane & 3;
    const int wr = warp >> 2, wc = warp & 3;
    const size_t r0 = (size_t)blockIdx.x * 128;
    const size_t n0 = (size_t)blockIdx.y * 128;

    // staging: 2 uint4 per thread over 128x64 halves
    const int rrA = tid >> 3,         ccA = (tid & 7) << 3;
    const int rrB = (tid + 512) >> 3, ccB = ((tid + 512) & 7) << 3;

    float oacc[2][4][4] = {};
    uint4 pX[2], pW[2];

    // prologue: stage e0 = 0
    *(uint4*)&Xs[rrA*SH + ccA] = *(const uint4*)(g_ctx   + (r0 + rrA)*EMBN + ccA);
    *(uint4*)&Xs[rrB*SH + ccB] = *(const uint4*)(g_ctx   + (r0 + rrB)*EMBN + ccB);
    *(uint4*)&Ws[rrA*SH + ccA] = *(const uint4*)(g_Wfc_h + (n0 + rrA)*EMBN + ccA);
    *(uint4*)&Ws[rrB*SH + ccB] = *(const uint4*)(g_Wfc_h + (n0 + rrB)*EMBN + ccB);

    for (int e = 0; e < 16; e++) {
        __syncthreads();
        // prefetch next e-block
        if (e < 15) {
            const int e0n = (e + 1) * 64;
            pX[0] = *(const uint4*)(g_ctx   + (r0 + rrA)*EMBN + e0n + ccA);
            pX[1] = *(const uint4*)(g_ctx   + (r0 + rrB)*EMBN + e0n + ccB);
            pW[0] = *(const uint4*)(g_Wfc_h + (n0 + rrA)*EMBN + e0n + ccA);
            pW[1] = *(const uint4*)(g_Wfc_h + (n0 + rrB)*EMBN + e0n + ccB);
        }
        // compute
        #pragma unroll
        for (int ks = 0; ks < 4; ks++) {
            uint32_t a[2][4];
            #pragma unroll
            for (int mi = 0; mi < 2; mi++) {
                int ar = wr*32 + mi*16 + g;
                a[mi][0] = ldh2(&Xs[ ar   *SH + ks*16 + 2*t    ]);
                a[mi][1] = ldh2(&Xs[(ar+8)*SH + ks*16 + 2*t    ]);
                a[mi][2] = ldh2(&Xs[ ar   *SH + ks*16 + 2*t + 8]);
                a[mi][3] = ldh2(&Xs[(ar+8)*SH + ks*16 + 2*t + 8]);
            }
            #pragma unroll
            for (int nt = 0; nt < 4; nt++) {
                const __half* Bb = Ws + (wc*32 + nt*8 + g)*SH;
                uint32_t b0 = ldh2(Bb + ks*16 + 2*t);
                uint32_t b1 = ldh2(Bb + ks*16 + 2*t + 8);
                #pragma unroll
                for (int mi = 0; mi < 2; mi++)
                    MMA_F16(oacc[mi][nt][0], oacc[mi][nt][1], oacc[mi][nt][2], oacc[mi][nt][3],
                            a[mi][0], a[mi][1], a[mi][2], a[mi][3], b0, b1);
            }
        }
        __syncthreads();
        if (e < 15) {
            *(uint4*)&Xs[rrA*SH + ccA] = pX[0];
            *(uint4*)&Xs[rrB*SH + ccB] = pX[1];
            *(uint4*)&Ws[rrA*SH + ccA] = pW[0];
            *(uint4*)&Ws[rrB*SH + ccB] = pW[1];
        }
    }

    #pragma unroll
    for (int mi = 0; mi < 2; mi++) {
        size_t ra = r0 + wr*32 + mi*16 + g;
        #pragma unroll
        for (int nt = 0; nt < 4; nt++) {
            size_t c = n0 + wc*32 + nt*8 + 2*t;
            float bv0 = bfc[c], bv1 = bfc[c+1];
            *(float2*)(out + ra*EMBN + c) =
                make_float2(oacc[mi][nt][0] + bv0, oacc[mi][nt][1] + bv1);
            *(float2*)(out + (ra+8)*EMBN + c) =
                make_float2(oacc[mi][nt][2] + bv0, oacc[mi][nt][3] + bv1);
        }
    }
}

// ---------------------------------------------------------------------------
extern "C" void kernel_launch(void* const* d_in, const int* in_sizes, int n_in,
                              void* d_out, int out_size)
{
    const float* query = (const float*)d_in[0];
    const float* key_  = (const float*)d_in[1];
    const float* value = (const float*)d_in[2];
    const int*   mask  = (const int*)d_in[3];
    const float* Wq = (const float*)d_in[4];
    const float* bq = (const float*)d_in[5];
    const float* Wk = (const float*)d_in[6];
    const float* bk = (const float*)d_in[7];
    const float* Wv = (const float*)d_in[8];
    const float* bv = (const float*)d_in[9];
    const float* Wfc = (const float*)d_in[10];
    const float* bfc = (const float*)d_in[11];
    const float* relk = (const float*)d_in[12];
    const float* relv = (const float*)d_in[13];
    float* out = (float*)d_out;

    cudaFuncSetAttribute(attn_kernel, cudaFuncAttributeMaxDynamicSharedMemorySize, ATT_SMEM_BYTES);

    prep_kernel<<<1024, 256>>>(relk, relv, Wfc, mask);
    proj_kernel<<<dim3(1024, 3, 1), 256>>>(query, key_, value, Wq, bq, Wk, bk, Wv, bv);
    attn_kernel<<<dim3(16, 16, 4), 512, ATT_SMEM_BYTES>>>();
    fc_kernel<<<dim3(32, 8, 1), 512>>>(bfc, out);
}